// round 4
// baseline (speedup 1.0000x reference)
#include <cuda_runtime.h>
#include <cstddef>

// Problem dims
constexpr int B_   = 2;
constexpr int SEQ  = 2048;
constexpr int DM   = 1024;   // d_model
constexpr int NH   = 16;     // heads
constexpr int DH   = 64;     // d_head
constexpr int MROWS = B_ * SEQ;          // 4096
constexpr size_t QKV_ELEMS = (size_t)B_ * NH * SEQ * DH;  // 4,194,304

// Scratch (device globals; no runtime allocation)
__device__ float g_q[QKV_ELEMS];   // [B,H,S,E]
__device__ float g_k[QKV_ELEMS];
__device__ float g_v[QKV_ELEMS];
__device__ float g_z[QKV_ELEMS];   // [b, s, h, e] == row-major [4096, 1024]

// ---------------------------------------------------------------------------
// tf32 helpers
// ---------------------------------------------------------------------------
__device__ __forceinline__ float f2tf(float f) {
    unsigned u;
    asm("cvt.rna.tf32.f32 %0, %1;" : "=r"(u) : "f"(f));
    return __uint_as_float(u);
}

__device__ __forceinline__ void mma_tf32(float* c,
                                         unsigned a0, unsigned a1, unsigned a2, unsigned a3,
                                         unsigned b0, unsigned b1) {
    asm("mma.sync.aligned.m16n8k8.row.col.f32.tf32.tf32.f32 "
        "{%0,%1,%2,%3}, {%4,%5,%6,%7}, {%8,%9}, {%0,%1,%2,%3};"
        : "+f"(c[0]), "+f"(c[1]), "+f"(c[2]), "+f"(c[3])
        : "r"(a0), "r"(a1), "r"(a2), "r"(a3), "r"(b0), "r"(b1));
}

// ---------------------------------------------------------------------------
// GEMM smem geometry (double-buffered)
// ---------------------------------------------------------------------------
constexpr int AS_LD = 36;
constexpr int BS_LD = 136;
constexpr int AS_F  = 128 * AS_LD;   // floats per A stage
constexpr int BS_F  = 32 * BS_LD;    // floats per B stage
constexpr size_t GEMM_SMEM_BYTES = (size_t)(2 * AS_F + 2 * BS_F) * sizeof(float);

// ---------------------------------------------------------------------------
// Kernel 1: fused QKV projection (tf32, reg prefetch + smem ping-pong).
// BM=BN=128, BK=32, 8 warps in 2(m) x 4(n); warp tile 64x32.
// ---------------------------------------------------------------------------
__global__ __launch_bounds__(256, 2) void qkv_gemm_tc(
    const float* __restrict__ x,
    const float* __restrict__ Wq, const float* __restrict__ bq,
    const float* __restrict__ Wk, const float* __restrict__ bk,
    const float* __restrict__ Wv, const float* __restrict__ bv)
{
    extern __shared__ float sg[];
    float* Asb = sg;                 // [2][128][AS_LD]
    float* Bsb = sg + 2 * AS_F;      // [2][32][BS_LD]

    const int pz = blockIdx.z;
    const float* W    = (pz == 0) ? Wq : (pz == 1) ? Wk : Wv;
    const float* bias = (pz == 0) ? bq : (pz == 1) ? bk : bv;
    float* outp       = (pz == 0) ? g_q : (pz == 1) ? g_k : g_v;

    const int n0 = blockIdx.x * 128;
    const int m0 = blockIdx.y * 128;
    const int tid  = threadIdx.x;
    const int wid  = tid >> 5;
    const int lane = tid & 31;
    const int wm = wid >> 2;
    const int wn = wid & 3;
    const int g  = lane >> 2;
    const int t  = lane & 3;

    const int arow = tid >> 3;
    const int akq  = (tid & 7) * 4;
    const int brow = tid >> 5;
    const int bnq  = (tid & 31) * 4;
    const int cb = n0 + bnq;
    const int hh = cb >> 6;
    const int ee = cb & 63;
    const float* Wbase = W + ((size_t)hh * DM) * DH + ee;
    const float* Abase = x + (size_t)m0 * DM;

    float acc[4][4][4] = {};
    float4 pa[4], pb[4];

    // prefetch tile 0 into regs
#pragma unroll
    for (int p = 0; p < 4; p++)
        pa[p] = *(const float4*)(Abase + (size_t)(p * 32 + arow) * DM + akq);
#pragma unroll
    for (int p = 0; p < 4; p++)
        pb[p] = *(const float4*)(Wbase + (size_t)(p * 8 + brow) * DH);

    // commit tile 0 -> stage 0
#pragma unroll
    for (int p = 0; p < 4; p++) {
        float4 c; c.x = f2tf(pa[p].x); c.y = f2tf(pa[p].y);
        c.z = f2tf(pa[p].z); c.w = f2tf(pa[p].w);
        *(float4*)&Asb[(p * 32 + arow) * AS_LD + akq] = c;
    }
#pragma unroll
    for (int p = 0; p < 4; p++) {
        float4 c; c.x = f2tf(pb[p].x); c.y = f2tf(pb[p].y);
        c.z = f2tf(pb[p].z); c.w = f2tf(pb[p].w);
        *(float4*)&Bsb[(p * 8 + brow) * BS_LD + bnq] = c;
    }
    __syncthreads();

    constexpr int NKT = DM / 32;   // 32
    for (int kt = 0; kt < NKT; ++kt) {
        const int cur = kt & 1;
        const float* As = Asb + cur * AS_F;
        const float* Bs = Bsb + cur * BS_F;

        if (kt < NKT - 1) {
            const int kb = (kt + 1) * 32;
#pragma unroll
            for (int p = 0; p < 4; p++)
                pa[p] = *(const float4*)(Abase + (size_t)(p * 32 + arow) * DM + kb + akq);
#pragma unroll
            for (int p = 0; p < 4; p++)
                pb[p] = *(const float4*)(Wbase + (size_t)(kb + p * 8 + brow) * DH);
        }

#pragma unroll
        for (int ch = 0; ch < 4; ch++) {
            const int ks = ch * 8;
            unsigned a[4][4];
#pragma unroll
            for (int mt = 0; mt < 4; mt++) {
                int r = wm * 64 + mt * 16 + g;
                a[mt][0] = __float_as_uint(As[r * AS_LD + ks + t]);
                a[mt][1] = __float_as_uint(As[(r + 8) * AS_LD + ks + t]);
                a[mt][2] = __float_as_uint(As[r * AS_LD + ks + t + 4]);
                a[mt][3] = __float_as_uint(As[(r + 8) * AS_LD + ks + t + 4]);
            }
#pragma unroll
            for (int nt = 0; nt < 4; nt++) {
                int cn = wn * 32 + nt * 8 + g;
                unsigned b0 = __float_as_uint(Bs[(ks + t) * BS_LD + cn]);
                unsigned b1 = __float_as_uint(Bs[(ks + t + 4) * BS_LD + cn]);
#pragma unroll
                for (int mt = 0; mt < 4; mt++)
                    mma_tf32(acc[mt][nt], a[mt][0], a[mt][1], a[mt][2], a[mt][3], b0, b1);
            }
        }

        if (kt < NKT - 1) {
            float* An = Asb + (1 - cur) * AS_F;
            float* Bn = Bsb + (1 - cur) * BS_F;
#pragma unroll
            for (int p = 0; p < 4; p++) {
                float4 c; c.x = f2tf(pa[p].x); c.y = f2tf(pa[p].y);
                c.z = f2tf(pa[p].z); c.w = f2tf(pa[p].w);
                *(float4*)&An[(p * 32 + arow) * AS_LD + akq] = c;
            }
#pragma unroll
            for (int p = 0; p < 4; p++) {
                float4 c; c.x = f2tf(pb[p].x); c.y = f2tf(pb[p].y);
                c.z = f2tf(pb[p].z); c.w = f2tf(pb[p].w);
                *(float4*)&Bn[(p * 8 + brow) * BS_LD + bnq] = c;
            }
            __syncthreads();
        }
    }

#pragma unroll
    for (int mt = 0; mt < 4; mt++) {
#pragma unroll
        for (int nt = 0; nt < 4; nt++) {
            int mg = m0 + wm * 64 + mt * 16 + g;
            int c  = n0 + wn * 32 + nt * 8 + t * 2;
            int h  = c >> 6;
            int e  = c & 63;
            float b0 = bias[c], b1 = bias[c + 1];
#pragma unroll
            for (int rr = 0; rr < 2; rr++) {
                int mgr = mg + rr * 8;
                int bb = mgr >> 11;
                int ss = mgr & (SEQ - 1);
                float2 w;
                w.x = acc[mt][nt][rr * 2 + 0] + b0;
                w.y = acc[mt][nt][rr * 2 + 1] + b1;
                *(float2*)(outp + ((((size_t)bb * NH + h) * SEQ + ss) * DH + e)) = w;
            }
        }
    }
}

// ---------------------------------------------------------------------------
// Kernel 2: causal flash attention (tf32 MMA, register softmax, K/V ping-pong).
// 8 warps; warp w owns query rows [w*16, w*16+16) x all 64 keys of the tile.
// Base-2 softmax: Q pre-scaled by log2(e)/8.
// ---------------------------------------------------------------------------
constexpr int QS_LD = 68;
constexpr int KV_LD = 72;
constexpr int KV_F  = 64 * KV_LD;     // floats per K or V stage
constexpr int SMEM_FLASH_FLOATS = 128 * QS_LD + 4 * KV_F;  // Q/P + 2xK + 2xV
constexpr size_t SMEM_FLASH_BYTES = SMEM_FLASH_FLOATS * sizeof(float);

__global__ __launch_bounds__(256, 2) void flash_attn_tc()
{
    extern __shared__ float smf[];
    float* Qs  = smf;                     // [128][QS_LD], later aliased as Ps
    float* Ktb = Qs + 128 * QS_LD;        // [2][64][KV_LD]  row e, col k
    float* Vsb = Ktb + 2 * KV_F;          // [2][64][KV_LD]  row k, col e

    const int bhid  = blockIdx.y;
    const int itile = (gridDim.x - 1) - blockIdx.x;  // heavy q-tiles first
    const int q0    = itile * 128;
    const float* Qg = g_q + (size_t)bhid * SEQ * DH;
    const float* Kg = g_k + (size_t)bhid * SEQ * DH;
    const float* Vg = g_v + (size_t)bhid * SEQ * DH;

    const int tid  = threadIdx.x;
    const int wid  = tid >> 5;
    const int lane = tid & 31;
    const int g  = lane >> 2;
    const int t  = lane & 3;
    const int r0 = wid * 16 + g;
    const int r1 = r0 + 8;

    constexpr float QSCALE = 0.125f * 1.44269504089f;  // log2(e)/sqrt(64)

    // --- load Q (scaled, tf32) into Qs ---
    {
        int q  = tid >> 1;
        int eh = (tid & 1) * 32;
        const float* src = Qg + (size_t)(q0 + q) * DH + eh;
#pragma unroll
        for (int i = 0; i < 8; i++) {
            float4 v = ((const float4*)src)[i];
            float4 c;
            c.x = f2tf(v.x * QSCALE); c.y = f2tf(v.y * QSCALE);
            c.z = f2tf(v.z * QSCALE); c.w = f2tf(v.w * QSCALE);
            *(float4*)&Qs[q * QS_LD + eh + i * 4] = c;
        }
    }

    // --- load K/V tile j=0 into stage 0 ---
    const int kk  = tid & 63;
    const int grp = tid >> 6;
    const float* Kgl = Kg + (size_t)kk * DH + grp * 16;
    const float* Vgl = Vg + (size_t)kk * DH + grp * 16;
    {
#pragma unroll
        for (int i = 0; i < 4; i++) {
            int e = grp * 16 + i * 4;
            float4 kv = ((const float4*)Kgl)[i];
            Ktb[(e + 0) * KV_LD + kk] = f2tf(kv.x);
            Ktb[(e + 1) * KV_LD + kk] = f2tf(kv.y);
            Ktb[(e + 2) * KV_LD + kk] = f2tf(kv.z);
            Ktb[(e + 3) * KV_LD + kk] = f2tf(kv.w);
            float4 vv = ((const float4*)Vgl)[i];
            float4 c; c.x = f2tf(vv.x); c.y = f2tf(vv.y);
            c.z = f2tf(vv.z); c.w = f2tf(vv.w);
            *(float4*)&Vsb[kk * KV_LD + e] = c;
        }
    }
    __syncthreads();

    // --- hoist Q fragments into registers; Qs becomes Ps ---
    unsigned qf[8][4];
#pragma unroll
    for (int ec = 0; ec < 8; ec++) {
        const int ks = ec * 8;
        qf[ec][0] = __float_as_uint(Qs[r0 * QS_LD + ks + t]);
        qf[ec][1] = __float_as_uint(Qs[r1 * QS_LD + ks + t]);
        qf[ec][2] = __float_as_uint(Qs[r0 * QS_LD + ks + t + 4]);
        qf[ec][3] = __float_as_uint(Qs[r1 * QS_LD + ks + t + 4]);
    }
    float* Ps = Qs;

    float m0 = -3.0e38f, m1 = -3.0e38f, l0 = 0.0f, l1 = 0.0f;
    float o[8][4] = {};

    const int jmax = 2 * itile + 1;
    for (int j = 0; j <= jmax; j++) {
        const int k0  = j * 64;
        const int cur = j & 1;
        const float* Kt = Ktb + cur * KV_F;
        const float* Vs = Vsb + cur * KV_F;

        // ---- Phase A: S = Q K^T  (16q x 64k per warp) ----
        float s[8][4] = {};
#pragma unroll
        for (int ec = 0; ec < 8; ec++) {
            const int ks = ec * 8;
#pragma unroll
            for (int nt = 0; nt < 8; nt++) {
                unsigned b0 = __float_as_uint(Kt[(ks + t) * KV_LD + nt * 8 + g]);
                unsigned b1 = __float_as_uint(Kt[(ks + t + 4) * KV_LD + nt * 8 + g]);
                mma_tf32(s[nt], qf[ec][0], qf[ec][1], qf[ec][2], qf[ec][3], b0, b1);
            }
        }

        // ---- mask ----
        if (j >= 2 * itile) {
            const int qg0 = q0 + r0, qg1 = q0 + r1;
#pragma unroll
            for (int nt = 0; nt < 8; nt++) {
#pragma unroll
                for (int cc = 0; cc < 2; cc++) {
                    int kg = k0 + nt * 8 + t * 2 + cc;
                    if (kg > qg0) s[nt][cc]     = -1.0e30f;
                    if (kg > qg1) s[nt][2 + cc] = -1.0e30f;
                }
            }
        }

        // ---- register online softmax, base 2 (quad reductions) ----
        float mx0 = -3.0e38f, mx1 = -3.0e38f;
#pragma unroll
        for (int nt = 0; nt < 8; nt++) {
            mx0 = fmaxf(mx0, fmaxf(s[nt][0], s[nt][1]));
            mx1 = fmaxf(mx1, fmaxf(s[nt][2], s[nt][3]));
        }
        mx0 = fmaxf(mx0, __shfl_xor_sync(0xFFFFFFFFu, mx0, 1));
        mx0 = fmaxf(mx0, __shfl_xor_sync(0xFFFFFFFFu, mx0, 2));
        mx1 = fmaxf(mx1, __shfl_xor_sync(0xFFFFFFFFu, mx1, 1));
        mx1 = fmaxf(mx1, __shfl_xor_sync(0xFFFFFFFFu, mx1, 2));
        mx0 = fmaxf(mx0, m0);
        mx1 = fmaxf(mx1, m1);
        const float sc0 = exp2f(m0 - mx0);
        const float sc1 = exp2f(m1 - mx1);
        m0 = mx0; m1 = mx1;

        float sum0 = 0.0f, sum1 = 0.0f;
#pragma unroll
        for (int nt = 0; nt < 8; nt++) {
            s[nt][0] = exp2f(s[nt][0] - mx0);
            s[nt][1] = exp2f(s[nt][1] - mx0);
            s[nt][2] = exp2f(s[nt][2] - mx1);
            s[nt][3] = exp2f(s[nt][3] - mx1);
            sum0 += s[nt][0] + s[nt][1];
            sum1 += s[nt][2] + s[nt][3];
        }
        sum0 += __shfl_xor_sync(0xFFFFFFFFu, sum0, 1);
        sum0 += __shfl_xor_sync(0xFFFFFFFFu, sum0, 2);
        sum1 += __shfl_xor_sync(0xFFFFFFFFu, sum1, 1);
        sum1 += __shfl_xor_sync(0xFFFFFFFFu, sum1, 2);
        l0 = l0 * sc0 + sum0;
        l1 = l1 * sc1 + sum1;

        // ---- store P (tf32) to per-warp rows of Ps ----
#pragma unroll
        for (int nt = 0; nt < 8; nt++) {
            const int kc = nt * 8 + t * 2;
            Ps[r0 * QS_LD + kc]     = f2tf(s[nt][0]);
            Ps[r0 * QS_LD + kc + 1] = f2tf(s[nt][1]);
            Ps[r1 * QS_LD + kc]     = f2tf(s[nt][2]);
            Ps[r1 * QS_LD + kc + 1] = f2tf(s[nt][3]);
        }
        __syncwarp();

        // ---- rescale O ----
#pragma unroll
        for (int nt = 0; nt < 8; nt++) {
            o[nt][0] *= sc0; o[nt][1] *= sc0;
            o[nt][2] *= sc1; o[nt][3] *= sc1;
        }

        // ---- prefetch next K/V tile into registers ----
        float4 pk[4], pv[4];
        if (j < jmax) {
            const size_t off = (size_t)(k0 + 64) * DH;
#pragma unroll
            for (int i = 0; i < 4; i++) {
                pk[i] = ((const float4*)(Kgl + off))[i];
                pv[i] = ((const float4*)(Vgl + off))[i];
            }
        }

        // ---- Phase C: O += P V  (16q x 64e per warp) ----
#pragma unroll
        for (int kc = 0; kc < 8; kc++) {
            const int ks = kc * 8;
            unsigned a0 = __float_as_uint(Ps[r0 * QS_LD + ks + t]);
            unsigned a1 = __float_as_uint(Ps[r1 * QS_LD + ks + t]);
            unsigned a2 = __float_as_uint(Ps[r0 * QS_LD + ks + t + 4]);
            unsigned a3 = __float_as_uint(Ps[r1 * QS_LD + ks + t + 4]);
#pragma unroll
            for (int nt = 0; nt < 8; nt++) {
                unsigned b0 = __float_as_uint(Vs[(ks + t) * KV_LD + nt * 8 + g]);
                unsigned b1 = __float_as_uint(Vs[(ks + t + 4) * KV_LD + nt * 8 + g]);
                mma_tf32(o[nt], a0, a1, a2, a3, b0, b1);
            }
        }

        // ---- commit prefetched K/V into the other stage; ONE sync ----
        if (j < jmax) {
            float* Kn = Ktb + (1 - cur) * KV_F;
            float* Vn = Vsb + (1 - cur) * KV_F;
#pragma unroll
            for (int i = 0; i < 4; i++) {
                int e = grp * 16 + i * 4;
                Kn[(e + 0) * KV_LD + kk] = f2tf(pk[i].x);
                Kn[(e + 1) * KV_LD + kk] = f2tf(pk[i].y);
                Kn[(e + 2) * KV_LD + kk] = f2tf(pk[i].z);
                Kn[(e + 3) * KV_LD + kk] = f2tf(pk[i].w);
                float4 c; c.x = f2tf(pv[i].x); c.y = f2tf(pv[i].y);
                c.z = f2tf(pv[i].z); c.w = f2tf(pv[i].w);
                *(float4*)&Vn[kk * KV_LD + e] = c;
            }
            __syncthreads();
        }
    }

    // ---- epilogue: z[b, q, h, e] = o / l ----
    const int bb = bhid >> 4;
    const int h  = bhid & 15;
    const float li0 = 1.0f / l0;
    const float li1 = 1.0f / l1;
#pragma unroll
    for (int nt = 0; nt < 8; nt++) {
        const int e = nt * 8 + t * 2;
        float2 w0, w1;
        w0.x = o[nt][0] * li0; w0.y = o[nt][1] * li0;
        w1.x = o[nt][2] * li1; w1.y = o[nt][3] * li1;
        size_t i0 = (((size_t)bb * SEQ + (q0 + r0)) * NH + h) * DH + e;
        size_t i1 = (((size_t)bb * SEQ + (q0 + r1)) * NH + h) * DH + e;
        *(float2*)(g_z + i0) = w0;
        *(float2*)(g_z + i1) = w1;
    }
}

// ---------------------------------------------------------------------------
// Kernel 3: output projection (tf32, reg prefetch + smem ping-pong).
// ---------------------------------------------------------------------------
__global__ __launch_bounds__(256, 2) void out_gemm_tc(
    const float* __restrict__ WO, const float* __restrict__ bO,
    float* __restrict__ out)
{
    extern __shared__ float sg[];
    float* Asb = sg;
    float* Bsb = sg + 2 * AS_F;

    const int n0 = blockIdx.x * 128;
    const int m0 = blockIdx.y * 128;
    const int tid  = threadIdx.x;
    const int wid  = tid >> 5;
    const int lane = tid & 31;
    const int wm = wid >> 2;
    const int wn = wid & 3;
    const int g  = lane >> 2;
    const int t  = lane & 3;

    const int arow = tid >> 3;
    const int akq  = (tid & 7) * 4;
    const int brow = tid >> 5;
    const int bnq  = (tid & 31) * 4;
    const float* Abase = g_z + (size_t)m0 * DM;
    const float* Bbase = WO + n0 + bnq;

    float acc[4][4][4] = {};
    float4 pa[4], pb[4];

#pragma unroll
    for (int p = 0; p < 4; p++)
        pa[p] = *(const float4*)(Abase + (size_t)(p * 32 + arow) * DM + akq);
#pragma unroll
    for (int p = 0; p < 4; p++)
        pb[p] = *(const float4*)(Bbase + (size_t)(p * 8 + brow) * DM);

#pragma unroll
    for (int p = 0; p < 4; p++) {
        float4 c; c.x = f2tf(pa[p].x); c.y = f2tf(pa[p].y);
        c.z = f2tf(pa[p].z); c.w = f2tf(pa[p].w);
        *(float4*)&Asb[(p * 32 + arow) * AS_LD + akq] = c;
    }
#pragma unroll
    for (int p = 0; p < 4; p++) {
        float4 c; c.x = f2tf(pb[p].x); c.y = f2tf(pb[p].y);
        c.z = f2tf(pb[p].z); c.w = f2tf(pb[p].w);
        *(float4*)&Bsb[(p * 8 + brow) * BS_LD + bnq] = c;
    }
    __syncthreads();

    constexpr int NKT = DM / 32;
    for (int kt = 0; kt < NKT; ++kt) {
        const int cur = kt & 1;
        const float* As = Asb + cur * AS_F;
        const float* Bs = Bsb + cur * BS_F;

        if (kt < NKT - 1) {
            const int kb = (kt + 1) * 32;
#pragma unroll
            for (int p = 0; p < 4; p++)
                pa[p] = *(const float4*)(Abase + (size_t)(p * 32 + arow) * DM + kb + akq);
#pragma unroll
            for (int p = 0; p < 4; p++)
                pb[p] = *(const float4*)(Bbase + (size_t)(kb + p * 8 + brow) * DM);
        }

#pragma unroll
        for (int ch = 0; ch < 4; ch++) {
            const int ks = ch * 8;
            unsigned a[4][4];
#pragma unroll
            for (int mt = 0; mt < 4; mt++) {
                int r = wm * 64 + mt * 16 + g;
                a[mt][0] = __float_as_uint(As[r * AS_LD + ks + t]);
                a[mt][1] = __float_as_uint(As[(r + 8) * AS_LD + ks + t]);
                a[mt][2] = __float_as_uint(As[r * AS_LD + ks + t + 4]);
                a[mt][3] = __float_as_uint(As[(r + 8) * AS_LD + ks + t + 4]);
            }
#pragma unroll
            for (int nt = 0; nt < 4; nt++) {
                int cn = wn * 32 + nt * 8 + g;
                unsigned b0 = __float_as_uint(Bs[(ks + t) * BS_LD + cn]);
                unsigned b1 = __float_as_uint(Bs[(ks + t + 4) * BS_LD + cn]);
#pragma unroll
                for (int mt = 0; mt < 4; mt++)
                    mma_tf32(acc[mt][nt], a[mt][0], a[mt][1], a[mt][2], a[mt][3], b0, b1);
            }
        }

        if (kt < NKT - 1) {
            float* An = Asb + (1 - cur) * AS_F;
            float* Bn = Bsb + (1 - cur) * BS_F;
#pragma unroll
            for (int p = 0; p < 4; p++) {
                float4 c; c.x = f2tf(pa[p].x); c.y = f2tf(pa[p].y);
                c.z = f2tf(pa[p].z); c.w = f2tf(pa[p].w);
                *(float4*)&An[(p * 32 + arow) * AS_LD + akq] = c;
            }
#pragma unroll
            for (int p = 0; p < 4; p++) {
                float4 c; c.x = f2tf(pb[p].x); c.y = f2tf(pb[p].y);
                c.z = f2tf(pb[p].z); c.w = f2tf(pb[p].w);
                *(float4*)&Bn[(p * 8 + brow) * BS_LD + bnq] = c;
            }
            __syncthreads();
        }
    }

#pragma unroll
    for (int mt = 0; mt < 4; mt++) {
#pragma unroll
        for (int nt = 0; nt < 4; nt++) {
            int mg = m0 + wm * 64 + mt * 16 + g;
            int c  = n0 + wn * 32 + nt * 8 + t * 2;
            float b0 = bO[c], b1 = bO[c + 1];
#pragma unroll
            for (int rr = 0; rr < 2; rr++) {
                float2 w;
                w.x = acc[mt][nt][rr * 2 + 0] + b0;
                w.y = acc[mt][nt][rr * 2 + 1] + b1;
                *(float2*)(out + (size_t)(mg + rr * 8) * DM + c) = w;
            }
        }
    }
}

// ---------------------------------------------------------------------------
// Launch
// inputs: 0=x, 1=W_Q, 2=b_Q, 3=W_K, 4=b_K, 5=W_V, 6=b_V, 7=W_O, 8=b_O
// ---------------------------------------------------------------------------
extern "C" void kernel_launch(void* const* d_in, const int* in_sizes, int n_in,
                              void* d_out, int out_size)
{
    const float* x  = (const float*)d_in[0];
    const float* Wq = (const float*)d_in[1];
    const float* bq = (const float*)d_in[2];
    const float* Wk = (const float*)d_in[3];
    const float* bk = (const float*)d_in[4];
    const float* Wv = (const float*)d_in[5];
    const float* bv = (const float*)d_in[6];
    const float* Wo = (const float*)d_in[7];
    const float* bo = (const float*)d_in[8];
    float* out = (float*)d_out;

    cudaFuncSetAttribute(qkv_gemm_tc,
                         cudaFuncAttributeMaxDynamicSharedMemorySize,
                         (int)GEMM_SMEM_BYTES);
    cudaFuncSetAttribute(out_gemm_tc,
                         cudaFuncAttributeMaxDynamicSharedMemorySize,
                         (int)GEMM_SMEM_BYTES);
    cudaFuncSetAttribute(flash_attn_tc,
                         cudaFuncAttributeMaxDynamicSharedMemorySize,
                         (int)SMEM_FLASH_BYTES);

    dim3 g1(DM / 128, MROWS / 128, 3);   // (8, 32, 3)
    qkv_gemm_tc<<<g1, 256, GEMM_SMEM_BYTES>>>(x, Wq, bq, Wk, bk, Wv, bv);

    dim3 g2(SEQ / 128, B_ * NH);          // (16, 32)
    flash_attn_tc<<<g2, 256, SMEM_FLASH_BYTES>>>();

    dim3 g3(DM / 128, MROWS / 128);       // (8, 32)
    out_gemm_tc<<<g3, 256, GEMM_SMEM_BYTES>>>(Wo, bo, out);
}

// round 5
// speedup vs baseline: 1.2001x; 1.2001x over previous
#include <cuda_runtime.h>
#include <cstddef>

// Problem dims
constexpr int B_   = 2;
constexpr int SEQ  = 2048;
constexpr int DM   = 1024;   // d_model
constexpr int NH   = 16;     // heads
constexpr int DH   = 64;     // d_head
constexpr int MROWS = B_ * SEQ;          // 4096
constexpr size_t QKV_ELEMS = (size_t)B_ * NH * SEQ * DH;  // 4,194,304

// Scratch (device globals; no runtime allocation)
__device__ float g_xt[(size_t)MROWS * DM];   // x, tf32
__device__ float g_wq[(size_t)DM * DM];      // W_Q as [k][n], tf32
__device__ float g_wk[(size_t)DM * DM];
__device__ float g_wv[(size_t)DM * DM];
__device__ float g_wo[(size_t)DM * DM];      // W_O [k][n], tf32
__device__ float g_q[QKV_ELEMS];             // [B,H,S,E], tf32, pre-scaled
__device__ float g_k[QKV_ELEMS];             // tf32
__device__ float g_v[QKV_ELEMS];             // tf32
__device__ float g_z[QKV_ELEMS];             // [b,s,h,e] row-major, tf32

constexpr float QSCALE = 0.125f * 1.44269504089f;  // log2(e)/sqrt(64)

// ---------------------------------------------------------------------------
// helpers
// ---------------------------------------------------------------------------
__device__ __forceinline__ float f2tf(float f) {
    unsigned u;
    asm("cvt.rna.tf32.f32 %0, %1;" : "=r"(u) : "f"(f));
    return __uint_as_float(u);
}
__device__ __forceinline__ float ex2(float x) {
    float y;
    asm("ex2.approx.f32 %0, %1;" : "=f"(y) : "f"(x));
    return y;
}
__device__ __forceinline__ void mma_tf32(float* c,
                                         unsigned a0, unsigned a1, unsigned a2, unsigned a3,
                                         unsigned b0, unsigned b1) {
    asm("mma.sync.aligned.m16n8k8.row.col.f32.tf32.tf32.f32 "
        "{%0,%1,%2,%3}, {%4,%5,%6,%7}, {%8,%9}, {%0,%1,%2,%3};"
        : "+f"(c[0]), "+f"(c[1]), "+f"(c[2]), "+f"(c[3])
        : "r"(a0), "r"(a1), "r"(a2), "r"(a3), "r"(b0), "r"(b1));
}
__device__ __forceinline__ unsigned smem_u32(const void* p) {
    return (unsigned)__cvta_generic_to_shared(p);
}
__device__ __forceinline__ void cp16(unsigned dst, const float* src) {
    asm volatile("cp.async.cg.shared.global [%0], [%1], 16;" :: "r"(dst), "l"(src));
}
__device__ __forceinline__ void cp_commit() {
    asm volatile("cp.async.commit_group;");
}
template<int N> __device__ __forceinline__ void cp_wait() {
    asm volatile("cp.async.wait_group %0;" :: "n"(N));
}

// ---------------------------------------------------------------------------
// Prologue: fp32 -> tf32 conversions (run once per launch, ~12us total)
// ---------------------------------------------------------------------------
__global__ void convert_x_kernel(const float* __restrict__ x) {
    int i = blockIdx.x * blockDim.x + threadIdx.x;   // 0..2^20-1 float4s
    float4 v = ((const float4*)x)[i];
    float4 c;
    c.x = f2tf(v.x); c.y = f2tf(v.y); c.z = f2tf(v.z); c.w = f2tf(v.w);
    ((float4*)g_xt)[i] = c;
}

__global__ void convert_w_kernel(const float* __restrict__ Wq,
                                 const float* __restrict__ Wk,
                                 const float* __restrict__ Wv,
                                 const float* __restrict__ Wo) {
    const int which = blockIdx.y;
    const int i4 = blockIdx.x * blockDim.x + threadIdx.x;   // 0..262143
    if (which == 3) {
        float4 v = ((const float4*)Wo)[i4];
        float4 c;
        c.x = f2tf(v.x); c.y = f2tf(v.y); c.z = f2tf(v.z); c.w = f2tf(v.w);
        ((float4*)g_wo)[i4] = c;
    } else {
        const float* W = (which == 0) ? Wq : (which == 1) ? Wk : Wv;
        float* dst = (which == 0) ? g_wq : (which == 1) ? g_wk : g_wv;
        int d = i4 >> 8;
        int n = (i4 & 255) * 4;
        int h = n >> 6, e = n & 63;
        float4 v = *(const float4*)(W + (size_t)h * DM * DH + (size_t)d * DH + e);
        float4 c;
        c.x = f2tf(v.x); c.y = f2tf(v.y); c.z = f2tf(v.z); c.w = f2tf(v.w);
        *(float4*)(dst + (size_t)d * DM + n) = c;
    }
}

// ---------------------------------------------------------------------------
// GEMM smem geometry: BM=128, BN=128, BK=32, 3-stage cp.async
// ---------------------------------------------------------------------------
constexpr int AS_LD = 36;
constexpr int BS_LD = 136;
constexpr int A_ST  = 128 * AS_LD;   // 4608 floats per A stage
constexpr int B_ST  = 32 * BS_LD;    // 4352 floats per B stage
constexpr size_t GEMM_SMEM_BYTES = (size_t)3 * (A_ST + B_ST) * sizeof(float); // 107,520

#define GEMM_ISSUE(Asrc_, Bsrc_, kt_, st_) do {                                    \
    const int kb_ = (kt_) * 32;                                                    \
    float* Ad_ = As + (st_) * A_ST;                                                \
    float* Bd_ = Bs + (st_) * B_ST;                                                \
    _Pragma("unroll")                                                              \
    for (int i_ = 0; i_ < 4; i_++) {                                               \
        int q_ = tid + 256 * i_;                                                   \
        int r_ = q_ >> 3, c_ = (q_ & 7) * 4;                                       \
        cp16(smem_u32(Ad_ + r_ * AS_LD + c_),                                      \
             (Asrc_) + (size_t)(m0 + r_) * DM + kb_ + c_);                         \
    }                                                                              \
    _Pragma("unroll")                                                              \
    for (int i_ = 0; i_ < 4; i_++) {                                               \
        int q_ = tid + 256 * i_;                                                   \
        int r_ = q_ >> 5, c_ = (q_ & 31) * 4;                                      \
        cp16(smem_u32(Bd_ + r_ * BS_LD + c_),                                      \
             (Bsrc_) + (size_t)(kb_ + r_) * DM + n0 + c_);                         \
    }                                                                              \
} while (0)

// compute one 32-k tile from stage st into acc[4][4][4]
#define GEMM_COMPUTE(st_) do {                                                     \
    const float* Asr = As + (st_) * A_ST;                                          \
    const float* Bsr = Bs + (st_) * B_ST;                                          \
    _Pragma("unroll")                                                              \
    for (int ch = 0; ch < 4; ch++) {                                               \
        const int ks = ch * 8;                                                     \
        unsigned a[4][4];                                                          \
        _Pragma("unroll")                                                          \
        for (int mt = 0; mt < 4; mt++) {                                           \
            int r = wm * 64 + mt * 16 + g;                                         \
            a[mt][0] = __float_as_uint(Asr[r * AS_LD + ks + t]);                   \
            a[mt][1] = __float_as_uint(Asr[(r + 8) * AS_LD + ks + t]);             \
            a[mt][2] = __float_as_uint(Asr[r * AS_LD + ks + t + 4]);               \
            a[mt][3] = __float_as_uint(Asr[(r + 8) * AS_LD + ks + t + 4]);         \
        }                                                                          \
        _Pragma("unroll")                                                          \
        for (int nt = 0; nt < 4; nt++) {                                           \
            int cn = wn * 32 + nt * 8 + g;                                         \
            unsigned b0 = __float_as_uint(Bsr[(ks + t) * BS_LD + cn]);             \
            unsigned b1 = __float_as_uint(Bsr[(ks + t + 4) * BS_LD + cn]);         \
            _Pragma("unroll")                                                      \
            for (int mt = 0; mt < 4; mt++)                                         \
                mma_tf32(acc[mt][nt], a[mt][0], a[mt][1], a[mt][2], a[mt][3],      \
                         b0, b1);                                                  \
        }                                                                          \
    }                                                                              \
} while (0)

// ---------------------------------------------------------------------------
// Kernel 1: fused QKV projection. Outputs tf32 (Q pre-scaled by QSCALE).
// ---------------------------------------------------------------------------
__global__ __launch_bounds__(256, 2) void qkv_gemm_tc(
    const float* __restrict__ bq, const float* __restrict__ bk,
    const float* __restrict__ bv)
{
    extern __shared__ float sg[];
    float* As = sg;
    float* Bs = sg + 3 * A_ST;

    const int pz = blockIdx.z;
    const float* gw   = (pz == 0) ? g_wq : (pz == 1) ? g_wk : g_wv;
    const float* bias = (pz == 0) ? bq : (pz == 1) ? bk : bv;
    float* outp       = (pz == 0) ? g_q : (pz == 1) ? g_k : g_v;
    const float oscale = (pz == 0) ? QSCALE : 1.0f;

    const int n0 = blockIdx.x * 128;
    const int m0 = blockIdx.y * 128;
    const int tid  = threadIdx.x;
    const int wid  = tid >> 5;
    const int lane = tid & 31;
    const int wm = wid >> 2;
    const int wn = wid & 3;
    const int g  = lane >> 2;
    const int t  = lane & 3;

    float acc[4][4][4] = {};

    GEMM_ISSUE(g_xt, gw, 0, 0); cp_commit();
    GEMM_ISSUE(g_xt, gw, 1, 1); cp_commit();

    constexpr int NKT = DM / 32;   // 32
    for (int kt = 0; kt < NKT; ++kt) {
        cp_wait<1>();
        __syncthreads();
        if (kt + 2 < NKT) GEMM_ISSUE(g_xt, gw, kt + 2, (kt + 2) % 3);
        cp_commit();
        GEMM_COMPUTE(kt % 3);
    }

    // Epilogue: out[((b*NH+h)*SEQ+s)*DH + e] = tf32((acc + bias) * oscale)
#pragma unroll
    for (int mt = 0; mt < 4; mt++) {
#pragma unroll
        for (int nt = 0; nt < 4; nt++) {
            int mg = m0 + wm * 64 + mt * 16 + g;
            int c  = n0 + wn * 32 + nt * 8 + t * 2;
            int h  = c >> 6;
            int e  = c & 63;
            float b0 = bias[c], b1 = bias[c + 1];
#pragma unroll
            for (int rr = 0; rr < 2; rr++) {
                int mgr = mg + rr * 8;
                int bb = mgr >> 11;
                int ss = mgr & (SEQ - 1);
                float2 w;
                w.x = f2tf((acc[mt][nt][rr * 2 + 0] + b0) * oscale);
                w.y = f2tf((acc[mt][nt][rr * 2 + 1] + b1) * oscale);
                *(float2*)(outp + ((((size_t)bb * NH + h) * SEQ + ss) * DH + e)) = w;
            }
        }
    }
}

// ---------------------------------------------------------------------------
// Kernel 2: causal flash attention.
// 8 warps; warp w owns query rows [w*16, w*16+16) x all 64 keys of the tile.
// All inputs pre-tf32 (Q pre-scaled). K/V natural [key][e] layout, cp.async
// double-buffered. P fragments built via shfl (no smem round-trip).
// ---------------------------------------------------------------------------
constexpr int QS_LD = 68;
constexpr int KS_LD = 68;   // K: phase-A b-frags bank-free (4g+t)
constexpr int VS_LD = 72;   // V: phase-C b-frags bank-free (8t+g)
constexpr int K_ST  = 64 * KS_LD;   // 4352
constexpr int V_ST  = 64 * VS_LD;   // 4608
constexpr size_t SMEM_FLASH_BYTES =
    (size_t)(128 * QS_LD + 2 * K_ST + 2 * V_ST) * sizeof(float);  // 106,496

#define FLASH_ISSUE(j_, st_) do {                                                  \
    const float* kp_ = Kg + (size_t)((j_) * 64 + kk) * DH + grp * 16;              \
    const float* vp_ = Vg + (size_t)((j_) * 64 + kk) * DH + grp * 16;              \
    float* Kd_ = Ks + (st_) * K_ST;                                                \
    float* Vd_ = Vs + (st_) * V_ST;                                                \
    _Pragma("unroll")                                                              \
    for (int i_ = 0; i_ < 4; i_++) {                                               \
        cp16(smem_u32(Kd_ + kk * KS_LD + grp * 16 + i_ * 4), kp_ + i_ * 4);        \
        cp16(smem_u32(Vd_ + kk * VS_LD + grp * 16 + i_ * 4), vp_ + i_ * 4);        \
    }                                                                              \
} while (0)

__global__ __launch_bounds__(256, 2) void flash_attn_tc()
{
    extern __shared__ float smf[];
    float* Qs = smf;                    // [128][QS_LD]
    float* Ks = Qs + 128 * QS_LD;       // [2][64][KS_LD]  natural [key][e]
    float* Vs = Ks + 2 * K_ST;          // [2][64][VS_LD]  natural [key][e]

    const int bhid  = blockIdx.y;
    const int itile = (gridDim.x - 1) - blockIdx.x;  // heavy q-tiles first
    const int q0    = itile * 128;
    const float* Qg = g_q + (size_t)bhid * SEQ * DH;
    const float* Kg = g_k + (size_t)bhid * SEQ * DH;
    const float* Vg = g_v + (size_t)bhid * SEQ * DH;

    const int tid  = threadIdx.x;
    const int wid  = tid >> 5;
    const int lane = tid & 31;
    const int g  = lane >> 2;
    const int t  = lane & 3;
    const int r0 = wid * 16 + g;
    const int r1 = r0 + 8;
    const int kk  = tid & 63;
    const int grp = tid >> 6;

    // issue K/V tile 0 into stage 0
    FLASH_ISSUE(0, 0);
    cp_commit();

    // plain-load Q (already tf32 + scaled)
    {
        int q  = tid >> 1;
        int eh = (tid & 1) * 32;
        const float* src = Qg + (size_t)(q0 + q) * DH + eh;
#pragma unroll
        for (int i = 0; i < 8; i++)
            *(float4*)&Qs[q * QS_LD + eh + i * 4] = ((const float4*)src)[i];
    }
    cp_wait<0>();
    __syncthreads();

    // hoist Q fragments into registers
    unsigned qf[8][4];
#pragma unroll
    for (int ec = 0; ec < 8; ec++) {
        const int ks = ec * 8;
        qf[ec][0] = __float_as_uint(Qs[r0 * QS_LD + ks + t]);
        qf[ec][1] = __float_as_uint(Qs[r1 * QS_LD + ks + t]);
        qf[ec][2] = __float_as_uint(Qs[r0 * QS_LD + ks + t + 4]);
        qf[ec][3] = __float_as_uint(Qs[r1 * QS_LD + ks + t + 4]);
    }

    float m0 = -3.0e38f, m1 = -3.0e38f, l0 = 0.0f, l1 = 0.0f;
    float o[8][4] = {};

    const int srcA = (g << 2) + (t >> 1);
    const int srcB = srcA + 2;
    const bool odd = (t & 1);

    const int jmax = 2 * itile + 1;
    for (int j = 0; j <= jmax; j++) {
        const int k0  = j * 64;
        const int cur = j & 1;

        // issue next tile into the other stage; overlaps all compute below
        if (j < jmax) FLASH_ISSUE(j + 1, 1 - cur);
        cp_commit();

        const float* Kc = Ks + cur * K_ST;
        const float* Vc = Vs + cur * V_ST;

        // ---- Phase A: S = Q K^T ----
        float s[8][4] = {};
#pragma unroll
        for (int ec = 0; ec < 8; ec++) {
            const int ks = ec * 8;
#pragma unroll
            for (int nt = 0; nt < 8; nt++) {
                unsigned b0 = __float_as_uint(Kc[(nt * 8 + g) * KS_LD + ks + t]);
                unsigned b1 = __float_as_uint(Kc[(nt * 8 + g) * KS_LD + ks + t + 4]);
                mma_tf32(s[nt], qf[ec][0], qf[ec][1], qf[ec][2], qf[ec][3], b0, b1);
            }
        }

        // ---- mask ----
        if (j >= 2 * itile) {
            const int qg0 = q0 + r0, qg1 = q0 + r1;
#pragma unroll
            for (int nt = 0; nt < 8; nt++) {
#pragma unroll
                for (int cc = 0; cc < 2; cc++) {
                    int kg = k0 + nt * 8 + t * 2 + cc;
                    if (kg > qg0) s[nt][cc]     = -1.0e30f;
                    if (kg > qg1) s[nt][2 + cc] = -1.0e30f;
                }
            }
        }

        // ---- register online softmax, base 2 ----
        float mx0 = -3.0e38f, mx1 = -3.0e38f;
#pragma unroll
        for (int nt = 0; nt < 8; nt++) {
            mx0 = fmaxf(mx0, fmaxf(s[nt][0], s[nt][1]));
            mx1 = fmaxf(mx1, fmaxf(s[nt][2], s[nt][3]));
        }
        mx0 = fmaxf(mx0, __shfl_xor_sync(0xFFFFFFFFu, mx0, 1));
        mx0 = fmaxf(mx0, __shfl_xor_sync(0xFFFFFFFFu, mx0, 2));
        mx1 = fmaxf(mx1, __shfl_xor_sync(0xFFFFFFFFu, mx1, 1));
        mx1 = fmaxf(mx1, __shfl_xor_sync(0xFFFFFFFFu, mx1, 2));
        mx0 = fmaxf(mx0, m0);
        mx1 = fmaxf(mx1, m1);
        const float sc0 = ex2(m0 - mx0);
        const float sc1 = ex2(m1 - mx1);
        m0 = mx0; m1 = mx1;

        float sum0 = 0.0f, sum1 = 0.0f;
#pragma unroll
        for (int nt = 0; nt < 8; nt++) {
            s[nt][0] = ex2(s[nt][0] - mx0);
            s[nt][1] = ex2(s[nt][1] - mx0);
            s[nt][2] = ex2(s[nt][2] - mx1);
            s[nt][3] = ex2(s[nt][3] - mx1);
            sum0 += s[nt][0] + s[nt][1];
            sum1 += s[nt][2] + s[nt][3];
        }
        sum0 += __shfl_xor_sync(0xFFFFFFFFu, sum0, 1);
        sum0 += __shfl_xor_sync(0xFFFFFFFFu, sum0, 2);
        sum1 += __shfl_xor_sync(0xFFFFFFFFu, sum1, 1);
        sum1 += __shfl_xor_sync(0xFFFFFFFFu, sum1, 2);
        l0 = l0 * sc0 + sum0;
        l1 = l1 * sc1 + sum1;

        // ---- rescale O ----
#pragma unroll
        for (int nt = 0; nt < 8; nt++) {
            o[nt][0] *= sc0; o[nt][1] *= sc0;
            o[nt][2] *= sc1; o[nt][3] *= sc1;
        }

        // ---- Phase C: O += P V, P a-frags via shfl (no smem) ----
        // s[kc][0..1] = P(r0, kc*8 + t*2 + {0,1}); s[kc][2..3] same for r1.
        // a-frag needs P(r, kc*8 + t) and P(r, kc*8 + t + 4).
#pragma unroll
        for (int kc = 0; kc < 8; kc++) {
            float v0 = __shfl_sync(0xFFFFFFFFu, s[kc][0], srcA);
            float v1 = __shfl_sync(0xFFFFFFFFu, s[kc][1], srcA);
            float v2 = __shfl_sync(0xFFFFFFFFu, s[kc][2], srcA);
            float v3 = __shfl_sync(0xFFFFFFFFu, s[kc][3], srcA);
            float w0 = __shfl_sync(0xFFFFFFFFu, s[kc][0], srcB);
            float w1 = __shfl_sync(0xFFFFFFFFu, s[kc][1], srcB);
            float w2 = __shfl_sync(0xFFFFFFFFu, s[kc][2], srcB);
            float w3 = __shfl_sync(0xFFFFFFFFu, s[kc][3], srcB);
            unsigned a0 = __float_as_uint(f2tf(odd ? v1 : v0));
            unsigned a1 = __float_as_uint(f2tf(odd ? v3 : v2));
            unsigned a2 = __float_as_uint(f2tf(odd ? w1 : w0));
            unsigned a3 = __float_as_uint(f2tf(odd ? w3 : w2));
            const int ks = kc * 8;
#pragma unroll
            for (int nt = 0; nt < 8; nt++) {
                unsigned b0 = __float_as_uint(Vc[(ks + t) * VS_LD + nt * 8 + g]);
                unsigned b1 = __float_as_uint(Vc[(ks + t + 4) * VS_LD + nt * 8 + g]);
                mma_tf32(o[nt], a0, a1, a2, a3, b0, b1);
            }
        }

        if (j < jmax) {
            cp_wait<0>();
            __syncthreads();
        }
    }

    // ---- epilogue: z[b, q, h, e] = tf32(o / l) ----
    const int bb = bhid >> 4;
    const int h  = bhid & 15;
    const float li0 = 1.0f / l0;
    const float li1 = 1.0f / l1;
#pragma unroll
    for (int nt = 0; nt < 8; nt++) {
        const int e = nt * 8 + t * 2;
        float2 w0, w1;
        w0.x = f2tf(o[nt][0] * li0); w0.y = f2tf(o[nt][1] * li0);
        w1.x = f2tf(o[nt][2] * li1); w1.y = f2tf(o[nt][3] * li1);
        size_t i0 = (((size_t)bb * SEQ + (q0 + r0)) * NH + h) * DH + e;
        size_t i1 = (((size_t)bb * SEQ + (q0 + r1)) * NH + h) * DH + e;
        *(float2*)(g_z + i0) = w0;
        *(float2*)(g_z + i1) = w1;
    }
}

// ---------------------------------------------------------------------------
// Kernel 3: output projection.  out = z[4096,1024] @ W_O[1024,1024] + b_O
// ---------------------------------------------------------------------------
__global__ __launch_bounds__(256, 2) void out_gemm_tc(
    const float* __restrict__ bO, float* __restrict__ out)
{
    extern __shared__ float sg[];
    float* As = sg;
    float* Bs = sg + 3 * A_ST;

    const int n0 = blockIdx.x * 128;
    const int m0 = blockIdx.y * 128;
    const int tid  = threadIdx.x;
    const int wid  = tid >> 5;
    const int lane = tid & 31;
    const int wm = wid >> 2;
    const int wn = wid & 3;
    const int g  = lane >> 2;
    const int t  = lane & 3;

    float acc[4][4][4] = {};

    GEMM_ISSUE(g_z, g_wo, 0, 0); cp_commit();
    GEMM_ISSUE(g_z, g_wo, 1, 1); cp_commit();

    constexpr int NKT = DM / 32;
    for (int kt = 0; kt < NKT; ++kt) {
        cp_wait<1>();
        __syncthreads();
        if (kt + 2 < NKT) GEMM_ISSUE(g_z, g_wo, kt + 2, (kt + 2) % 3);
        cp_commit();
        GEMM_COMPUTE(kt % 3);
    }

#pragma unroll
    for (int mt = 0; mt < 4; mt++) {
#pragma unroll
        for (int nt = 0; nt < 4; nt++) {
            int mg = m0 + wm * 64 + mt * 16 + g;
            int c  = n0 + wn * 32 + nt * 8 + t * 2;
            float b0 = bO[c], b1 = bO[c + 1];
#pragma unroll
            for (int rr = 0; rr < 2; rr++) {
                float2 w;
                w.x = acc[mt][nt][rr * 2 + 0] + b0;
                w.y = acc[mt][nt][rr * 2 + 1] + b1;
                *(float2*)(out + (size_t)(mg + rr * 8) * DM + c) = w;
            }
        }
    }
}

// ---------------------------------------------------------------------------
// Launch
// inputs: 0=x, 1=W_Q, 2=b_Q, 3=W_K, 4=b_K, 5=W_V, 6=b_V, 7=W_O, 8=b_O
// ---------------------------------------------------------------------------
extern "C" void kernel_launch(void* const* d_in, const int* in_sizes, int n_in,
                              void* d_out, int out_size)
{
    const float* x  = (const float*)d_in[0];
    const float* Wq = (const float*)d_in[1];
    const float* bq = (const float*)d_in[2];
    const float* Wk = (const float*)d_in[3];
    const float* bk = (const float*)d_in[4];
    const float* Wv = (const float*)d_in[5];
    const float* bv = (const float*)d_in[6];
    const float* Wo = (const float*)d_in[7];
    const float* bo = (const float*)d_in[8];
    float* out = (float*)d_out;

    cudaFuncSetAttribute(qkv_gemm_tc,
                         cudaFuncAttributeMaxDynamicSharedMemorySize,
                         (int)GEMM_SMEM_BYTES);
    cudaFuncSetAttribute(out_gemm_tc,
                         cudaFuncAttributeMaxDynamicSharedMemorySize,
                         (int)GEMM_SMEM_BYTES);
    cudaFuncSetAttribute(flash_attn_tc,
                         cudaFuncAttributeMaxDynamicSharedMemorySize,
                         (int)SMEM_FLASH_BYTES);

    convert_x_kernel<<<(MROWS * DM / 4) / 256, 256>>>(x);
    convert_w_kernel<<<dim3((DM * DM / 4) / 256, 4), 256>>>(Wq, Wk, Wv, Wo);

    dim3 g1(DM / 128, MROWS / 128, 3);   // (8, 32, 3)
    qkv_gemm_tc<<<g1, 256, GEMM_SMEM_BYTES>>>(bq, bk, bv);

    dim3 g2(SEQ / 128, B_ * NH);          // (16, 32)
    flash_attn_tc<<<g2, 256, SMEM_FLASH_BYTES>>>();

    dim3 g3(DM / 128, MROWS / 128);       // (8, 32)
    out_gemm_tc<<<g3, 256, GEMM_SMEM_BYTES>>>(bo, out);
}

// round 6
// speedup vs baseline: 1.7646x; 1.4704x over previous
#include <cuda_runtime.h>
#include <cuda_fp16.h>
#include <cstddef>

// Problem dims
constexpr int B_   = 2;
constexpr int SEQ  = 2048;
constexpr int DM   = 1024;   // d_model
constexpr int NH   = 16;     // heads
constexpr int DH   = 64;     // d_head
constexpr int MROWS = B_ * SEQ;          // 4096
constexpr size_t QKV_ELEMS = (size_t)B_ * NH * SEQ * DH;  // 4,194,304

// Scratch (device globals; no runtime allocation)
__device__ __half g_x [(size_t)MROWS * DM];   // x fp16 [m][k]
__device__ __half g_wq[(size_t)DM * DM];      // W_Q transposed [n=c][k=d]
__device__ __half g_wk[(size_t)DM * DM];
__device__ __half g_wv[(size_t)DM * DM];
__device__ __half g_wo[(size_t)DM * DM];      // W_O transposed [n=d][k=c]
__device__ __half g_q [QKV_ELEMS];            // [b,h,s,e], pre-scaled
__device__ __half g_k [QKV_ELEMS];            // [b,h,s,e]
__device__ __half g_v [QKV_ELEMS];            // TRANSPOSED [b,h,e,s]
__device__ __half g_z [QKV_ELEMS];            // [b,s,h,e] == [m][k]

constexpr float QSCALE = 0.125f * 1.44269504089f;  // log2(e)/sqrt(64)

// ---------------------------------------------------------------------------
// helpers
// ---------------------------------------------------------------------------
__device__ __forceinline__ float ex2(float x) {
    float y;
    asm("ex2.approx.f32 %0, %1;" : "=f"(y) : "f"(x));
    return y;
}
// pack two fp32 -> half2 (lo at lower address semantics)
__device__ __forceinline__ unsigned pack_h2(float lo, float hi) {
    unsigned d;
    asm("cvt.rn.f16x2.f32 %0, %1, %2;" : "=r"(d) : "f"(hi), "f"(lo));
    return d;
}
__device__ __forceinline__ unsigned ldh2(const __half* p) {
    return *(const unsigned*)p;
}
__device__ __forceinline__ void mma_f16(float* c,
                                        unsigned a0, unsigned a1, unsigned a2, unsigned a3,
                                        unsigned b0, unsigned b1) {
    asm("mma.sync.aligned.m16n8k16.row.col.f32.f16.f16.f32 "
        "{%0,%1,%2,%3}, {%4,%5,%6,%7}, {%8,%9}, {%0,%1,%2,%3};"
        : "+f"(c[0]), "+f"(c[1]), "+f"(c[2]), "+f"(c[3])
        : "r"(a0), "r"(a1), "r"(a2), "r"(a3), "r"(b0), "r"(b1));
}
__device__ __forceinline__ unsigned smem_u32(const void* p) {
    return (unsigned)__cvta_generic_to_shared(p);
}
__device__ __forceinline__ void cp16(unsigned dst, const void* src) {
    asm volatile("cp.async.cg.shared.global [%0], [%1], 16;" :: "r"(dst), "l"(src));
}
__device__ __forceinline__ void cp_commit() {
    asm volatile("cp.async.commit_group;");
}
template<int N> __device__ __forceinline__ void cp_wait() {
    asm volatile("cp.async.wait_group %0;" :: "n"(N));
}

// ---------------------------------------------------------------------------
// Prologue: fp32 -> fp16 conversions + weight transposes (once per launch)
// ---------------------------------------------------------------------------
__global__ void convert_x_kernel(const float* __restrict__ x) {
    int i = blockIdx.x * blockDim.x + threadIdx.x;    // 1M float4
    float4 v = ((const float4*)x)[i];
    uint2 o;
    o.x = pack_h2(v.x, v.y);
    o.y = pack_h2(v.z, v.w);
    ((uint2*)g_x)[i] = o;
}

__global__ void convert_w_kernel(const float* __restrict__ Wq,
                                 const float* __restrict__ Wk,
                                 const float* __restrict__ Wv,
                                 const float* __restrict__ Wo) {
    const int which = blockIdx.y;
    const int idx = blockIdx.x * blockDim.x + threadIdx.x;   // 0..524287
    if (which == 3) {
        int d  = idx & 1023;
        int cp = idx >> 10;       // 0..511
        float f0 = Wo[(size_t)(2 * cp)     * DM + d];
        float f1 = Wo[(size_t)(2 * cp + 1) * DM + d];
        *(unsigned*)&g_wo[(size_t)d * DM + 2 * cp] = pack_h2(f0, f1);
    } else {
        int c  = idx & 1023;
        int dp = idx >> 10;       // 0..511
        const float* W = (which == 0) ? Wq : (which == 1) ? Wk : Wv;
        __half* dst    = (which == 0) ? g_wq : (which == 1) ? g_wk : g_wv;
        int h = c >> 6, e = c & 63;
        float f0 = W[(size_t)h * DM * DH + (size_t)(2 * dp)     * DH + e];
        float f1 = W[(size_t)h * DM * DH + (size_t)(2 * dp + 1) * DH + e];
        *(unsigned*)&dst[(size_t)c * DM + 2 * dp] = pack_h2(f0, f1);
    }
}

// ---------------------------------------------------------------------------
// GEMM geometry: BM=128, BN=128, BK=32 (fp16), 3-stage cp.async.
// A smem [m][k] 128x(32+8); B smem [n][k] 128x(32+8). 8 warps 2(m)x4(n).
// ---------------------------------------------------------------------------
constexpr int AS_LD = 40;            // halves per row (32 data + 8 pad)
constexpr int BS_LD = 40;
constexpr int A_ST  = 128 * AS_LD;   // 5120 halves per stage
constexpr int B_ST  = 128 * BS_LD;
constexpr size_t GEMM_SMEM_BYTES = (size_t)3 * (A_ST + B_ST) * 2;  // 61,440

#define GEMM_ISSUE(Asrc_, Bsrc_, kt_, st_) do {                                   \
    const int kb_ = (kt_) * 32;                                                   \
    __half* Ad_ = As + (st_) * A_ST;                                              \
    __half* Bd_ = Bs + (st_) * B_ST;                                              \
    int r_ = tid >> 1, c_ = (tid & 1) * 16;                                       \
    cp16(smem_u32(Ad_ + r_ * AS_LD + c_),                                         \
         (Asrc_) + (size_t)(m0 + r_) * DM + kb_ + c_);                            \
    cp16(smem_u32(Ad_ + r_ * AS_LD + c_ + 8),                                     \
         (Asrc_) + (size_t)(m0 + r_) * DM + kb_ + c_ + 8);                        \
    cp16(smem_u32(Bd_ + r_ * BS_LD + c_),                                         \
         (Bsrc_) + (size_t)(n0 + r_) * DM + kb_ + c_);                            \
    cp16(smem_u32(Bd_ + r_ * BS_LD + c_ + 8),                                     \
         (Bsrc_) + (size_t)(n0 + r_) * DM + kb_ + c_ + 8);                        \
} while (0)

#define GEMM_COMPUTE(st_) do {                                                    \
    const __half* Asr = As + (st_) * A_ST;                                        \
    const __half* Bsr = Bs + (st_) * B_ST;                                        \
    _Pragma("unroll")                                                             \
    for (int ck = 0; ck < 2; ck++) {                                              \
        const int ko = ck * 16 + 2 * t;                                           \
        unsigned a[4][4];                                                         \
        _Pragma("unroll")                                                         \
        for (int mt = 0; mt < 4; mt++) {                                          \
            int r = wm * 64 + mt * 16 + g;                                        \
            a[mt][0] = ldh2(Asr + r * AS_LD + ko);                                \
            a[mt][1] = ldh2(Asr + (r + 8) * AS_LD + ko);                          \
            a[mt][2] = ldh2(Asr + r * AS_LD + ko + 8);                            \
            a[mt][3] = ldh2(Asr + (r + 8) * AS_LD + ko + 8);                      \
        }                                                                         \
        _Pragma("unroll")                                                         \
        for (int nt = 0; nt < 4; nt++) {                                          \
            int cn = wn * 32 + nt * 8 + g;                                        \
            unsigned b0 = ldh2(Bsr + cn * BS_LD + ko);                            \
            unsigned b1 = ldh2(Bsr + cn * BS_LD + ko + 8);                        \
            _Pragma("unroll")                                                     \
            for (int mt = 0; mt < 4; mt++)                                        \
                mma_f16(acc[mt][nt], a[mt][0], a[mt][1], a[mt][2], a[mt][3],      \
                        b0, b1);                                                  \
        }                                                                         \
    }                                                                             \
} while (0)

// ---------------------------------------------------------------------------
// Kernel 1: fused QKV projection (fp16). Q pre-scaled; V stored transposed.
// ---------------------------------------------------------------------------
__global__ __launch_bounds__(256, 2) void qkv_gemm_tc(
    const float* __restrict__ bq, const float* __restrict__ bk,
    const float* __restrict__ bv)
{
    extern __shared__ __half sg[];
    __half* As = sg;
    __half* Bs = sg + 3 * A_ST;

    const int pz = blockIdx.z;
    const __half* gw  = (pz == 0) ? g_wq : (pz == 1) ? g_wk : g_wv;
    const float* bias = (pz == 0) ? bq : (pz == 1) ? bk : bv;

    const int n0 = blockIdx.x * 128;
    const int m0 = blockIdx.y * 128;
    const int tid  = threadIdx.x;
    const int wid  = tid >> 5;
    const int lane = tid & 31;
    const int wm = wid >> 2;
    const int wn = wid & 3;
    const int g  = lane >> 2;
    const int t  = lane & 3;

    float acc[4][4][4] = {};

    GEMM_ISSUE(g_x, gw, 0, 0); cp_commit();
    GEMM_ISSUE(g_x, gw, 1, 1); cp_commit();

    constexpr int NKT = DM / 32;   // 32
    for (int kt = 0; kt < NKT; ++kt) {
        cp_wait<1>();
        __syncthreads();
        if (kt + 2 < NKT) GEMM_ISSUE(g_x, gw, kt + 2, (kt + 2) % 3);
        cp_commit();
        GEMM_COMPUTE(kt % 3);
    }

#pragma unroll
    for (int mt = 0; mt < 4; mt++) {
#pragma unroll
        for (int nt = 0; nt < 4; nt++) {
            int mg = m0 + wm * 64 + mt * 16 + g;
            int c  = n0 + wn * 32 + nt * 8 + t * 2;
            int h  = c >> 6;
            int e  = c & 63;
            float b0 = bias[c], b1 = bias[c + 1];
#pragma unroll
            for (int rr = 0; rr < 2; rr++) {
                int mgr = mg + rr * 8;
                int bb = mgr >> 11;
                int ss = mgr & (SEQ - 1);
                float v0 = acc[mt][nt][rr * 2 + 0] + b0;
                float v1 = acc[mt][nt][rr * 2 + 1] + b1;
                if (pz == 0) {
                    v0 *= QSCALE; v1 *= QSCALE;
                    size_t idx = ((((size_t)bb * NH + h) * SEQ + ss) * DH + e);
                    *(unsigned*)&g_q[idx] = pack_h2(v0, v1);
                } else if (pz == 1) {
                    size_t idx = ((((size_t)bb * NH + h) * SEQ + ss) * DH + e);
                    *(unsigned*)&g_k[idx] = pack_h2(v0, v1);
                } else {
                    // transposed: g_v[(bh*DH + e)*SEQ + ss]
                    size_t base = (((size_t)bb * NH + h) * DH + e) * SEQ + ss;
                    g_v[base]       = __float2half_rn(v0);
                    g_v[base + SEQ] = __float2half_rn(v1);
                }
            }
        }
    }
}

// ---------------------------------------------------------------------------
// Kernel 2: causal flash attention, fp16 MMA, pipelined (S(j+1) overlaps
// softmax(j)+PV(j)). P packs directly from registers (C-frag == A-frag).
// 8 warps x 16 query rows; key tile 64.
// ---------------------------------------------------------------------------
constexpr int QS_LD = 72;
constexpr int KS_LD = 72;
constexpr int VT_LD = 72;
constexpr int K_ST  = 64 * KS_LD;
constexpr int V_ST  = 64 * VT_LD;
constexpr size_t SMEM_FLASH_BYTES =
    (size_t)(128 * QS_LD + 2 * K_ST + 2 * V_ST) * 2;  // 55,296

#define FLASH_ISSUE_K(j_, st_) do {                                              \
    const __half* kp_ = Kg + (size_t)((j_) * 64 + kk) * DH + grp * 16;           \
    __half* kd_ = Ks + (st_) * K_ST + kk * KS_LD + grp * 16;                     \
    cp16(smem_u32(kd_), kp_);                                                    \
    cp16(smem_u32(kd_ + 8), kp_ + 8);                                            \
} while (0)

#define FLASH_ISSUE_V(j_, st_) do {                                              \
    const __half* vp_ = Vg + (size_t)kk * SEQ + (j_) * 64 + grp * 16;            \
    __half* vd_ = Vt + (st_) * V_ST + kk * VT_LD + grp * 16;                     \
    cp16(smem_u32(vd_), vp_);                                                    \
    cp16(smem_u32(vd_ + 8), vp_ + 8);                                            \
} while (0)

#define PHASE_A(dst_, Kc_) do {                                                  \
    _Pragma("unroll")                                                            \
    for (int ec = 0; ec < 4; ec++) {                                             \
        const int ko = ec * 16 + 2 * t;                                          \
        unsigned a0 = ldh2(Qs + r0 * QS_LD + ko);                                \
        unsigned a1 = ldh2(Qs + r1 * QS_LD + ko);                                \
        unsigned a2 = ldh2(Qs + r0 * QS_LD + ko + 8);                            \
        unsigned a3 = ldh2(Qs + r1 * QS_LD + ko + 8);                            \
        _Pragma("unroll")                                                        \
        for (int nt = 0; nt < 8; nt++) {                                         \
            unsigned b0 = ldh2((Kc_) + (nt * 8 + g) * KS_LD + ko);               \
            unsigned b1 = ldh2((Kc_) + (nt * 8 + g) * KS_LD + ko + 8);           \
            mma_f16(dst_[nt], a0, a1, a2, a3, b0, b1);                           \
        }                                                                        \
    }                                                                            \
} while (0)

__global__ __launch_bounds__(256, 2) void flash_attn_tc()
{
    extern __shared__ __half smh[];
    __half* Qs = smh;                    // [128][QS_LD]
    __half* Ks = Qs + 128 * QS_LD;       // [2][64][KS_LD]  rows key, cols e
    __half* Vt = Ks + 2 * K_ST;          // [2][64][VT_LD]  rows e, cols key

    const int bhid  = blockIdx.y;
    const int itile = (gridDim.x - 1) - blockIdx.x;  // heavy q-tiles first
    const int q0    = itile * 128;
    const __half* Qg = g_q + (size_t)bhid * SEQ * DH;
    const __half* Kg = g_k + (size_t)bhid * SEQ * DH;
    const __half* Vg = g_v + (size_t)bhid * DH * SEQ;   // transposed [e][s]

    const int tid  = threadIdx.x;
    const int wid  = tid >> 5;
    const int lane = tid & 31;
    const int g  = lane >> 2;
    const int t  = lane & 3;
    const int r0 = wid * 16 + g;
    const int r1 = r0 + 8;
    const int kk  = tid & 63;
    const int grp = tid >> 6;

    const int jmax = 2 * itile + 1;

    // prologue: K0+V0 (G0), K1 (G1)
    FLASH_ISSUE_K(0, 0);
    FLASH_ISSUE_V(0, 0);
    cp_commit();
    FLASH_ISSUE_K(1, 1);
    cp_commit();

    // plain-load Q (fp16, pre-scaled)
    {
        int q  = tid >> 1;
        int eh = (tid & 1) * 32;
        const __half* src = Qg + (size_t)(q0 + q) * DH + eh;
#pragma unroll
        for (int i = 0; i < 4; i++)
            *(uint4*)(Qs + q * QS_LD + eh + i * 8) = ((const uint4*)src)[i];
    }
    cp_wait<0>();
    __syncthreads();

    float m0 = -3.0e38f, m1 = -3.0e38f, l0 = 0.0f, l1 = 0.0f;
    float o[8][4] = {};

    // S for tile 0
    float s[8][4] = {};
    PHASE_A(s, Ks);

    for (int j = 0; j <= jmax; j++) {
        const int k0  = j * 64;
        const int cur = j & 1;

        cp_wait<0>();
        __syncthreads();
        if (j + 2 <= jmax) FLASH_ISSUE_K(j + 2, cur);
        if (j + 1 <= jmax) FLASH_ISSUE_V(j + 1, 1 - cur);
        cp_commit();

        // ---- S for tile j+1 (overlaps softmax below in the tensor pipe) ----
        float s2[8][4] = {};
        if (j < jmax) {
            const __half* Kn = Ks + (1 - cur) * K_ST;
            PHASE_A(s2, Kn);
        }

        // ---- mask tile j ----
        if (j >= 2 * itile) {
            const int qg0 = q0 + r0, qg1 = q0 + r1;
#pragma unroll
            for (int nt = 0; nt < 8; nt++) {
#pragma unroll
                for (int cc = 0; cc < 2; cc++) {
                    int kg = k0 + nt * 8 + t * 2 + cc;
                    if (kg > qg0) s[nt][cc]     = -1.0e30f;
                    if (kg > qg1) s[nt][2 + cc] = -1.0e30f;
                }
            }
        }

        // ---- register online softmax, base 2 ----
        float mx0 = -3.0e38f, mx1 = -3.0e38f;
#pragma unroll
        for (int nt = 0; nt < 8; nt++) {
            mx0 = fmaxf(mx0, fmaxf(s[nt][0], s[nt][1]));
            mx1 = fmaxf(mx1, fmaxf(s[nt][2], s[nt][3]));
        }
        mx0 = fmaxf(mx0, __shfl_xor_sync(0xFFFFFFFFu, mx0, 1));
        mx0 = fmaxf(mx0, __shfl_xor_sync(0xFFFFFFFFu, mx0, 2));
        mx1 = fmaxf(mx1, __shfl_xor_sync(0xFFFFFFFFu, mx1, 1));
        mx1 = fmaxf(mx1, __shfl_xor_sync(0xFFFFFFFFu, mx1, 2));
        mx0 = fmaxf(mx0, m0);
        mx1 = fmaxf(mx1, m1);
        const float sc0 = ex2(m0 - mx0);
        const float sc1 = ex2(m1 - mx1);
        m0 = mx0; m1 = mx1;

        float sum0 = 0.0f, sum1 = 0.0f;
#pragma unroll
        for (int nt = 0; nt < 8; nt++) {
            s[nt][0] = ex2(s[nt][0] - mx0);
            s[nt][1] = ex2(s[nt][1] - mx0);
            s[nt][2] = ex2(s[nt][2] - mx1);
            s[nt][3] = ex2(s[nt][3] - mx1);
            sum0 += s[nt][0] + s[nt][1];
            sum1 += s[nt][2] + s[nt][3];
        }
        sum0 += __shfl_xor_sync(0xFFFFFFFFu, sum0, 1);
        sum0 += __shfl_xor_sync(0xFFFFFFFFu, sum0, 2);
        sum1 += __shfl_xor_sync(0xFFFFFFFFu, sum1, 1);
        sum1 += __shfl_xor_sync(0xFFFFFFFFu, sum1, 2);
        l0 = l0 * sc0 + sum0;
        l1 = l1 * sc1 + sum1;

        // ---- rescale O ----
#pragma unroll
        for (int nt = 0; nt < 8; nt++) {
            o[nt][0] *= sc0; o[nt][1] *= sc0;
            o[nt][2] *= sc1; o[nt][3] *= sc1;
        }

        // ---- Phase C: O += P V  (P packs straight from registers) ----
        const __half* Vc = Vt + cur * V_ST;
#pragma unroll
        for (int kc = 0; kc < 4; kc++) {
            unsigned a0 = pack_h2(s[2 * kc][0],     s[2 * kc][1]);
            unsigned a1 = pack_h2(s[2 * kc][2],     s[2 * kc][3]);
            unsigned a2 = pack_h2(s[2 * kc + 1][0], s[2 * kc + 1][1]);
            unsigned a3 = pack_h2(s[2 * kc + 1][2], s[2 * kc + 1][3]);
            const int ko = kc * 16 + 2 * t;
#pragma unroll
            for (int nt = 0; nt < 8; nt++) {
                unsigned b0 = ldh2(Vc + (nt * 8 + g) * VT_LD + ko);
                unsigned b1 = ldh2(Vc + (nt * 8 + g) * VT_LD + ko + 8);
                mma_f16(o[nt], a0, a1, a2, a3, b0, b1);
            }
        }

        // ---- advance score buffer ----
        if (j < jmax) {
#pragma unroll
            for (int nt = 0; nt < 8; nt++) {
#pragma unroll
                for (int q2 = 0; q2 < 4; q2++) s[nt][q2] = s2[nt][q2];
            }
        }
    }

    // ---- epilogue: z[b, q, h, e] = fp16(o / l) ----
    const int bb = bhid >> 4;
    const int h  = bhid & 15;
    const float li0 = 1.0f / l0;
    const float li1 = 1.0f / l1;
#pragma unroll
    for (int nt = 0; nt < 8; nt++) {
        const int e = nt * 8 + t * 2;
        size_t i0 = (((size_t)bb * SEQ + (q0 + r0)) * NH + h) * DH + e;
        size_t i1 = (((size_t)bb * SEQ + (q0 + r1)) * NH + h) * DH + e;
        *(unsigned*)&g_z[i0] = pack_h2(o[nt][0] * li0, o[nt][1] * li0);
        *(unsigned*)&g_z[i1] = pack_h2(o[nt][2] * li1, o[nt][3] * li1);
    }
}

// ---------------------------------------------------------------------------
// Kernel 3: output projection.  out = z[4096,1024] @ W_O^T-layout + b_O
// ---------------------------------------------------------------------------
__global__ __launch_bounds__(256, 2) void out_gemm_tc(
    const float* __restrict__ bO, float* __restrict__ out)
{
    extern __shared__ __half sg[];
    __half* As = sg;
    __half* Bs = sg + 3 * A_ST;

    const int n0 = blockIdx.x * 128;
    const int m0 = blockIdx.y * 128;
    const int tid  = threadIdx.x;
    const int wid  = tid >> 5;
    const int lane = tid & 31;
    const int wm = wid >> 2;
    const int wn = wid & 3;
    const int g  = lane >> 2;
    const int t  = lane & 3;

    float acc[4][4][4] = {};

    GEMM_ISSUE(g_z, g_wo, 0, 0); cp_commit();
    GEMM_ISSUE(g_z, g_wo, 1, 1); cp_commit();

    constexpr int NKT = DM / 32;
    for (int kt = 0; kt < NKT; ++kt) {
        cp_wait<1>();
        __syncthreads();
        if (kt + 2 < NKT) GEMM_ISSUE(g_z, g_wo, kt + 2, (kt + 2) % 3);
        cp_commit();
        GEMM_COMPUTE(kt % 3);
    }

#pragma unroll
    for (int mt = 0; mt < 4; mt++) {
#pragma unroll
        for (int nt = 0; nt < 4; nt++) {
            int mg = m0 + wm * 64 + mt * 16 + g;
            int c  = n0 + wn * 32 + nt * 8 + t * 2;
            float b0 = bO[c], b1 = bO[c + 1];
#pragma unroll
            for (int rr = 0; rr < 2; rr++) {
                float2 w;
                w.x = acc[mt][nt][rr * 2 + 0] + b0;
                w.y = acc[mt][nt][rr * 2 + 1] + b1;
                *(float2*)(out + (size_t)(mg + rr * 8) * DM + c) = w;
            }
        }
    }
}

// ---------------------------------------------------------------------------
// Launch
// inputs: 0=x, 1=W_Q, 2=b_Q, 3=W_K, 4=b_K, 5=W_V, 6=b_V, 7=W_O, 8=b_O
// ---------------------------------------------------------------------------
extern "C" void kernel_launch(void* const* d_in, const int* in_sizes, int n_in,
                              void* d_out, int out_size)
{
    const float* x  = (const float*)d_in[0];
    const float* Wq = (const float*)d_in[1];
    const float* bq = (const float*)d_in[2];
    const float* Wk = (const float*)d_in[3];
    const float* bk = (const float*)d_in[4];
    const float* Wv = (const float*)d_in[5];
    const float* bv = (const float*)d_in[6];
    const float* Wo = (const float*)d_in[7];
    const float* bo = (const float*)d_in[8];
    float* out = (float*)d_out;

    cudaFuncSetAttribute(qkv_gemm_tc,
                         cudaFuncAttributeMaxDynamicSharedMemorySize,
                         (int)GEMM_SMEM_BYTES);
    cudaFuncSetAttribute(out_gemm_tc,
                         cudaFuncAttributeMaxDynamicSharedMemorySize,
                         (int)GEMM_SMEM_BYTES);
    cudaFuncSetAttribute(flash_attn_tc,
                         cudaFuncAttributeMaxDynamicSharedMemorySize,
                         (int)SMEM_FLASH_BYTES);

    convert_x_kernel<<<(MROWS * DM / 4) / 256, 256>>>(x);
    convert_w_kernel<<<dim3((DM * DM / 2) / 256, 4), 256>>>(Wq, Wk, Wv, Wo);

    dim3 g1(DM / 128, MROWS / 128, 3);   // (8, 32, 3)
    qkv_gemm_tc<<<g1, 256, GEMM_SMEM_BYTES>>>(bq, bk, bv);

    dim3 g2(SEQ / 128, B_ * NH);          // (16, 32)
    flash_attn_tc<<<g2, 256, SMEM_FLASH_BYTES>>>();

    dim3 g3(DM / 128, MROWS / 128);       // (8, 32)
    out_gemm_tc<<<g3, 256, GEMM_SMEM_BYTES>>>(bo, out);
}

// round 7
// speedup vs baseline: 1.9943x; 1.1301x over previous
#include <cuda_runtime.h>
#include <cuda_fp16.h>
#include <cstddef>

// Problem dims
constexpr int B_   = 2;
constexpr int SEQ  = 2048;
constexpr int DM   = 1024;   // d_model
constexpr int NH   = 16;     // heads
constexpr int DH   = 64;     // d_head
constexpr int MROWS = B_ * SEQ;          // 4096
constexpr size_t QKV_ELEMS = (size_t)B_ * NH * SEQ * DH;  // 4,194,304

// Scratch (device globals; no runtime allocation)
__device__ __half g_x [(size_t)MROWS * DM];   // x fp16 [m][k]
__device__ __half g_wq[(size_t)DM * DM];      // W_Q transposed [n=c][k=d]
__device__ __half g_wk[(size_t)DM * DM];
__device__ __half g_wv[(size_t)DM * DM];
__device__ __half g_wo[(size_t)DM * DM];      // W_O transposed [n=d][k=c]
__device__ __half g_q [QKV_ELEMS];            // [b,h,s,e], pre-scaled
__device__ __half g_k [QKV_ELEMS];            // [b,h,s,e]
__device__ __half g_v [QKV_ELEMS];            // TRANSPOSED [b,h,e,s]
__device__ __half g_z [QKV_ELEMS];            // [b,s,h,e] == [m][k]

constexpr float QSCALE = 0.125f * 1.44269504089f;  // log2(e)/sqrt(64)

// ---------------------------------------------------------------------------
// helpers
// ---------------------------------------------------------------------------
__device__ __forceinline__ float ex2(float x) {
    float y;
    asm("ex2.approx.f32 %0, %1;" : "=f"(y) : "f"(x));
    return y;
}
__device__ __forceinline__ unsigned pack_h2(float lo, float hi) {
    unsigned d;
    asm("cvt.rn.f16x2.f32 %0, %1, %2;" : "=r"(d) : "f"(hi), "f"(lo));
    return d;
}
__device__ __forceinline__ void mma_f16(float* c,
                                        unsigned a0, unsigned a1, unsigned a2, unsigned a3,
                                        unsigned b0, unsigned b1) {
    asm("mma.sync.aligned.m16n8k16.row.col.f32.f16.f16.f32 "
        "{%0,%1,%2,%3}, {%4,%5,%6,%7}, {%8,%9}, {%0,%1,%2,%3};"
        : "+f"(c[0]), "+f"(c[1]), "+f"(c[2]), "+f"(c[3])
        : "r"(a0), "r"(a1), "r"(a2), "r"(a3), "r"(b0), "r"(b1));
}
__device__ __forceinline__ unsigned smem_u32(const void* p) {
    return (unsigned)__cvta_generic_to_shared(p);
}
__device__ __forceinline__ void ldsm4(unsigned r[4], const __half* p) {
    unsigned a = smem_u32(p);
    asm volatile("ldmatrix.sync.aligned.m8n8.x4.shared.b16 {%0,%1,%2,%3}, [%4];"
                 : "=r"(r[0]), "=r"(r[1]), "=r"(r[2]), "=r"(r[3]) : "r"(a));
}
__device__ __forceinline__ void cp16(unsigned dst, const void* src) {
    asm volatile("cp.async.cg.shared.global [%0], [%1], 16;" :: "r"(dst), "l"(src));
}
__device__ __forceinline__ void cp_commit() {
    asm volatile("cp.async.commit_group;");
}
template<int N> __device__ __forceinline__ void cp_wait() {
    asm volatile("cp.async.wait_group %0;" :: "n"(N));
}

// ---------------------------------------------------------------------------
// Prologue: fp32 -> fp16 conversions + weight transposes
// ---------------------------------------------------------------------------
__global__ void convert_x_kernel(const float* __restrict__ x) {
    int i = blockIdx.x * blockDim.x + threadIdx.x;    // 1M float4
    float4 v = ((const float4*)x)[i];
    uint2 o;
    o.x = pack_h2(v.x, v.y);
    o.y = pack_h2(v.z, v.w);
    ((uint2*)g_x)[i] = o;
}

__global__ void convert_w_kernel(const float* __restrict__ Wq,
                                 const float* __restrict__ Wk,
                                 const float* __restrict__ Wv,
                                 const float* __restrict__ Wo) {
    const int which = blockIdx.y;
    const int idx = blockIdx.x * blockDim.x + threadIdx.x;   // 0..524287
    if (which == 3) {
        int d  = idx & 1023;
        int cp = idx >> 10;       // 0..511
        float f0 = Wo[(size_t)(2 * cp)     * DM + d];
        float f1 = Wo[(size_t)(2 * cp + 1) * DM + d];
        *(unsigned*)&g_wo[(size_t)d * DM + 2 * cp] = pack_h2(f0, f1);
    } else {
        int c  = idx & 1023;
        int dp = idx >> 10;       // 0..511
        const float* W = (which == 0) ? Wq : (which == 1) ? Wk : Wv;
        __half* dst    = (which == 0) ? g_wq : (which == 1) ? g_wk : g_wv;
        int h = c >> 6, e = c & 63;
        float f0 = W[(size_t)h * DM * DH + (size_t)(2 * dp)     * DH + e];
        float f1 = W[(size_t)h * DM * DH + (size_t)(2 * dp + 1) * DH + e];
        *(unsigned*)&dst[(size_t)c * DM + 2 * dp] = pack_h2(f0, f1);
    }
}

// ---------------------------------------------------------------------------
// GEMM geometry: BM=128, BN=128, BK=32 (fp16), 3-stage cp.async, ldmatrix.
// ---------------------------------------------------------------------------
constexpr int AS_LD = 40;            // halves per row (32 data + 8 pad)
constexpr int BS_LD = 40;
constexpr int A_ST  = 128 * AS_LD;
constexpr int B_ST  = 128 * BS_LD;
constexpr size_t GEMM_SMEM_BYTES = (size_t)3 * (A_ST + B_ST) * 2;  // 61,440

#define GEMM_ISSUE(Asrc_, Bsrc_, kt_, st_) do {                                   \
    const int kb_ = (kt_) * 32;                                                   \
    __half* Ad_ = As + (st_) * A_ST;                                              \
    __half* Bd_ = Bs + (st_) * B_ST;                                              \
    int r_ = tid >> 1, c_ = (tid & 1) * 16;                                       \
    cp16(smem_u32(Ad_ + r_ * AS_LD + c_),                                         \
         (Asrc_) + (size_t)(m0 + r_) * DM + kb_ + c_);                            \
    cp16(smem_u32(Ad_ + r_ * AS_LD + c_ + 8),                                     \
         (Asrc_) + (size_t)(m0 + r_) * DM + kb_ + c_ + 8);                        \
    cp16(smem_u32(Bd_ + r_ * BS_LD + c_),                                         \
         (Bsrc_) + (size_t)(n0 + r_) * DM + kb_ + c_);                            \
    cp16(smem_u32(Bd_ + r_ * BS_LD + c_ + 8),                                     \
         (Bsrc_) + (size_t)(n0 + r_) * DM + kb_ + c_ + 8);                        \
} while (0)

// lane-address constants (defined in each kernel):
//  fa_r = lane & 15, fa_h = ((lane>>4)&1)*8           -> A frags
//  fb_r = ((lane>>4)&1)*8 + (lane&7), fb_h = ((lane>>3)&1)*8  -> B frags
#define GEMM_COMPUTE(st_) do {                                                    \
    const __half* Asr = As + (st_) * A_ST;                                        \
    const __half* Bsr = Bs + (st_) * B_ST;                                        \
    _Pragma("unroll")                                                             \
    for (int ck = 0; ck < 2; ck++) {                                              \
        unsigned a[4][4];                                                         \
        _Pragma("unroll")                                                         \
        for (int mt = 0; mt < 4; mt++)                                            \
            ldsm4(a[mt], Asr + (wm * 64 + mt * 16 + fa_r) * AS_LD                 \
                          + ck * 16 + fa_h);                                      \
        _Pragma("unroll")                                                         \
        for (int c2 = 0; c2 < 2; c2++) {                                          \
            unsigned bf[4];                                                       \
            ldsm4(bf, Bsr + (wn * 32 + c2 * 16 + fb_r) * BS_LD                    \
                       + ck * 16 + fb_h);                                         \
            _Pragma("unroll")                                                     \
            for (int mt = 0; mt < 4; mt++) {                                      \
                mma_f16(acc[mt][2 * c2],     a[mt][0], a[mt][1], a[mt][2],        \
                        a[mt][3], bf[0], bf[1]);                                  \
                mma_f16(acc[mt][2 * c2 + 1], a[mt][0], a[mt][1], a[mt][2],        \
                        a[mt][3], bf[2], bf[3]);                                  \
            }                                                                     \
        }                                                                         \
    }                                                                             \
} while (0)

// ---------------------------------------------------------------------------
// Kernel 1: fused QKV projection (fp16). Q pre-scaled; V stored transposed.
// ---------------------------------------------------------------------------
__global__ __launch_bounds__(256, 2) void qkv_gemm_tc(
    const float* __restrict__ bq, const float* __restrict__ bk,
    const float* __restrict__ bv)
{
    extern __shared__ __half sg[];
    __half* As = sg;
    __half* Bs = sg + 3 * A_ST;

    const int pz = blockIdx.z;
    const __half* gw  = (pz == 0) ? g_wq : (pz == 1) ? g_wk : g_wv;
    const float* bias = (pz == 0) ? bq : (pz == 1) ? bk : bv;

    const int n0 = blockIdx.x * 128;
    const int m0 = blockIdx.y * 128;
    const int tid  = threadIdx.x;
    const int wid  = tid >> 5;
    const int lane = tid & 31;
    const int wm = wid >> 2;
    const int wn = wid & 3;
    const int g  = lane >> 2;
    const int t  = lane & 3;
    const int fa_r = lane & 15;
    const int fa_h = ((lane >> 4) & 1) * 8;
    const int fb_r = ((lane >> 4) & 1) * 8 + (lane & 7);
    const int fb_h = ((lane >> 3) & 1) * 8;

    float acc[4][4][4] = {};

    GEMM_ISSUE(g_x, gw, 0, 0); cp_commit();
    GEMM_ISSUE(g_x, gw, 1, 1); cp_commit();

    constexpr int NKT = DM / 32;   // 32
    for (int kt = 0; kt < NKT; ++kt) {
        cp_wait<1>();
        __syncthreads();
        if (kt + 2 < NKT) GEMM_ISSUE(g_x, gw, kt + 2, (kt + 2) % 3);
        cp_commit();
        GEMM_COMPUTE(kt % 3);
    }

#pragma unroll
    for (int mt = 0; mt < 4; mt++) {
#pragma unroll
        for (int nt = 0; nt < 4; nt++) {
            int mg = m0 + wm * 64 + mt * 16 + g;
            int c  = n0 + wn * 32 + nt * 8 + t * 2;
            int h  = c >> 6;
            int e  = c & 63;
            float b0 = bias[c], b1 = bias[c + 1];
#pragma unroll
            for (int rr = 0; rr < 2; rr++) {
                int mgr = mg + rr * 8;
                int bb = mgr >> 11;
                int ss = mgr & (SEQ - 1);
                float v0 = acc[mt][nt][rr * 2 + 0] + b0;
                float v1 = acc[mt][nt][rr * 2 + 1] + b1;
                if (pz == 0) {
                    v0 *= QSCALE; v1 *= QSCALE;
                    size_t idx = ((((size_t)bb * NH + h) * SEQ + ss) * DH + e);
                    *(unsigned*)&g_q[idx] = pack_h2(v0, v1);
                } else if (pz == 1) {
                    size_t idx = ((((size_t)bb * NH + h) * SEQ + ss) * DH + e);
                    *(unsigned*)&g_k[idx] = pack_h2(v0, v1);
                } else {
                    size_t base = (((size_t)bb * NH + h) * DH + e) * SEQ + ss;
                    g_v[base]       = __float2half_rn(v0);
                    g_v[base + SEQ] = __float2half_rn(v1);
                }
            }
        }
    }
}

// ---------------------------------------------------------------------------
// Kernel 2: causal flash attention, fp16 MMA + ldmatrix, pipelined.
// 8 warps x 16 query rows; key tile 64. P packs straight from registers.
// ---------------------------------------------------------------------------
constexpr int QS_LD = 72;
constexpr int KS_LD = 72;
constexpr int VT_LD = 72;
constexpr int K_ST  = 64 * KS_LD;
constexpr int V_ST  = 64 * VT_LD;
constexpr size_t SMEM_FLASH_BYTES =
    (size_t)(128 * QS_LD + 2 * K_ST + 2 * V_ST) * 2;  // 55,296

#define FLASH_ISSUE_K(j_, st_) do {                                              \
    const __half* kp_ = Kg + (size_t)((j_) * 64 + kk) * DH + grp * 16;           \
    __half* kd_ = Ks + (st_) * K_ST + kk * KS_LD + grp * 16;                     \
    cp16(smem_u32(kd_), kp_);                                                    \
    cp16(smem_u32(kd_ + 8), kp_ + 8);                                            \
} while (0)

#define FLASH_ISSUE_V(j_, st_) do {                                              \
    const __half* vp_ = Vg + (size_t)kk * SEQ + (j_) * 64 + grp * 16;            \
    __half* vd_ = Vt + (st_) * V_ST + kk * VT_LD + grp * 16;                     \
    cp16(smem_u32(vd_), vp_);                                                    \
    cp16(smem_u32(vd_ + 8), vp_ + 8);                                            \
} while (0)

#define PHASE_A(dst_, Kc_) do {                                                  \
    _Pragma("unroll")                                                            \
    for (int ec = 0; ec < 4; ec++) {                                             \
        _Pragma("unroll")                                                        \
        for (int c2 = 0; c2 < 4; c2++) {                                         \
            unsigned bf[4];                                                      \
            ldsm4(bf, (Kc_) + (c2 * 16 + fb_r) * KS_LD + ec * 16 + fb_h);        \
            mma_f16(dst_[2 * c2],     qf[ec][0], qf[ec][1], qf[ec][2],           \
                    qf[ec][3], bf[0], bf[1]);                                    \
            mma_f16(dst_[2 * c2 + 1], qf[ec][0], qf[ec][1], qf[ec][2],           \
                    qf[ec][3], bf[2], bf[3]);                                    \
        }                                                                        \
    }                                                                            \
} while (0)

__global__ __launch_bounds__(256, 2) void flash_attn_tc()
{
    extern __shared__ __half smh[];
    __half* Qs = smh;                    // [128][QS_LD]
    __half* Ks = Qs + 128 * QS_LD;       // [2][64][KS_LD]  rows key, cols e
    __half* Vt = Ks + 2 * K_ST;          // [2][64][VT_LD]  rows e, cols key

    const int bhid  = blockIdx.y;
    const int itile = (gridDim.x - 1) - blockIdx.x;  // heavy q-tiles first
    const int q0    = itile * 128;
    const __half* Qg = g_q + (size_t)bhid * SEQ * DH;
    const __half* Kg = g_k + (size_t)bhid * SEQ * DH;
    const __half* Vg = g_v + (size_t)bhid * DH * SEQ;   // transposed [e][s]

    const int tid  = threadIdx.x;
    const int wid  = tid >> 5;
    const int lane = tid & 31;
    const int g  = lane >> 2;
    const int t  = lane & 3;
    const int r0 = wid * 16 + g;
    const int r1 = r0 + 8;
    const int kk  = tid & 63;
    const int grp = tid >> 6;
    const int fa_r = lane & 15;
    const int fa_h = ((lane >> 4) & 1) * 8;
    const int fb_r = ((lane >> 4) & 1) * 8 + (lane & 7);
    const int fb_h = ((lane >> 3) & 1) * 8;

    const int jmax = 2 * itile + 1;

    // prologue: K0+V0 (G0), K1 (G1)
    FLASH_ISSUE_K(0, 0);
    FLASH_ISSUE_V(0, 0);
    cp_commit();
    FLASH_ISSUE_K(1, 1);
    cp_commit();

    // plain-load Q (fp16, pre-scaled)
    {
        int q  = tid >> 1;
        int eh = (tid & 1) * 32;
        const __half* src = Qg + (size_t)(q0 + q) * DH + eh;
#pragma unroll
        for (int i = 0; i < 4; i++)
            *(uint4*)(Qs + q * QS_LD + eh + i * 8) = ((const uint4*)src)[i];
    }
    cp_wait<0>();
    __syncthreads();

    // hoist Q fragments via ldmatrix
    unsigned qf[4][4];
#pragma unroll
    for (int ec = 0; ec < 4; ec++)
        ldsm4(qf[ec], Qs + (wid * 16 + fa_r) * QS_LD + ec * 16 + fa_h);

    float m0 = -3.0e38f, m1 = -3.0e38f, l0 = 0.0f, l1 = 0.0f;
    float o[8][4] = {};

    // S for tile 0
    float s[8][4] = {};
    PHASE_A(s, Ks);

    for (int j = 0; j <= jmax; j++) {
        const int k0  = j * 64;
        const int cur = j & 1;

        cp_wait<0>();
        __syncthreads();
        if (j + 2 <= jmax) FLASH_ISSUE_K(j + 2, cur);
        if (j + 1 <= jmax) FLASH_ISSUE_V(j + 1, 1 - cur);
        cp_commit();

        // ---- S for tile j+1 (overlaps softmax below) ----
        float s2[8][4] = {};
        if (j < jmax) {
            const __half* Kn = Ks + (1 - cur) * K_ST;
            PHASE_A(s2, Kn);
        }

        // ---- mask tile j ----
        if (j >= 2 * itile) {
            const int qg0 = q0 + r0, qg1 = q0 + r1;
#pragma unroll
            for (int nt = 0; nt < 8; nt++) {
#pragma unroll
                for (int cc = 0; cc < 2; cc++) {
                    int kg = k0 + nt * 8 + t * 2 + cc;
                    if (kg > qg0) s[nt][cc]     = -1.0e30f;
                    if (kg > qg1) s[nt][2 + cc] = -1.0e30f;
                }
            }
        }

        // ---- register online softmax, base 2 ----
        float mx0 = -3.0e38f, mx1 = -3.0e38f;
#pragma unroll
        for (int nt = 0; nt < 8; nt++) {
            mx0 = fmaxf(mx0, fmaxf(s[nt][0], s[nt][1]));
            mx1 = fmaxf(mx1, fmaxf(s[nt][2], s[nt][3]));
        }
        mx0 = fmaxf(mx0, __shfl_xor_sync(0xFFFFFFFFu, mx0, 1));
        mx0 = fmaxf(mx0, __shfl_xor_sync(0xFFFFFFFFu, mx0, 2));
        mx1 = fmaxf(mx1, __shfl_xor_sync(0xFFFFFFFFu, mx1, 1));
        mx1 = fmaxf(mx1, __shfl_xor_sync(0xFFFFFFFFu, mx1, 2));
        mx0 = fmaxf(mx0, m0);
        mx1 = fmaxf(mx1, m1);
        const float sc0 = ex2(m0 - mx0);
        const float sc1 = ex2(m1 - mx1);
        m0 = mx0; m1 = mx1;

        float sum0 = 0.0f, sum1 = 0.0f;
#pragma unroll
        for (int nt = 0; nt < 8; nt++) {
            s[nt][0] = ex2(s[nt][0] - mx0);
            s[nt][1] = ex2(s[nt][1] - mx0);
            s[nt][2] = ex2(s[nt][2] - mx1);
            s[nt][3] = ex2(s[nt][3] - mx1);
            sum0 += s[nt][0] + s[nt][1];
            sum1 += s[nt][2] + s[nt][3];
        }
        sum0 += __shfl_xor_sync(0xFFFFFFFFu, sum0, 1);
        sum0 += __shfl_xor_sync(0xFFFFFFFFu, sum0, 2);
        sum1 += __shfl_xor_sync(0xFFFFFFFFu, sum1, 1);
        sum1 += __shfl_xor_sync(0xFFFFFFFFu, sum1, 2);
        l0 = l0 * sc0 + sum0;
        l1 = l1 * sc1 + sum1;

        // ---- rescale O ----
#pragma unroll
        for (int nt = 0; nt < 8; nt++) {
            o[nt][0] *= sc0; o[nt][1] *= sc0;
            o[nt][2] *= sc1; o[nt][3] *= sc1;
        }

        // ---- Phase C: O += P V ----
        const __half* Vc = Vt + cur * V_ST;
#pragma unroll
        for (int kc = 0; kc < 4; kc++) {
            unsigned a0 = pack_h2(s[2 * kc][0],     s[2 * kc][1]);
            unsigned a1 = pack_h2(s[2 * kc][2],     s[2 * kc][3]);
            unsigned a2 = pack_h2(s[2 * kc + 1][0], s[2 * kc + 1][1]);
            unsigned a3 = pack_h2(s[2 * kc + 1][2], s[2 * kc + 1][3]);
#pragma unroll
            for (int c2 = 0; c2 < 4; c2++) {
                unsigned bf[4];
                ldsm4(bf, Vc + (c2 * 16 + fb_r) * VT_LD + kc * 16 + fb_h);
                mma_f16(o[2 * c2],     a0, a1, a2, a3, bf[0], bf[1]);
                mma_f16(o[2 * c2 + 1], a0, a1, a2, a3, bf[2], bf[3]);
            }
        }

        // ---- advance score buffer ----
        if (j < jmax) {
#pragma unroll
            for (int nt = 0; nt < 8; nt++) {
#pragma unroll
                for (int q2 = 0; q2 < 4; q2++) s[nt][q2] = s2[nt][q2];
            }
        }
    }

    // ---- epilogue: z[b, q, h, e] = fp16(o / l) ----
    const int bb = bhid >> 4;
    const int h  = bhid & 15;
    const float li0 = 1.0f / l0;
    const float li1 = 1.0f / l1;
#pragma unroll
    for (int nt = 0; nt < 8; nt++) {
        const int e = nt * 8 + t * 2;
        size_t i0 = (((size_t)bb * SEQ + (q0 + r0)) * NH + h) * DH + e;
        size_t i1 = (((size_t)bb * SEQ + (q0 + r1)) * NH + h) * DH + e;
        *(unsigned*)&g_z[i0] = pack_h2(o[nt][0] * li0, o[nt][1] * li0);
        *(unsigned*)&g_z[i1] = pack_h2(o[nt][2] * li1, o[nt][3] * li1);
    }
}

// ---------------------------------------------------------------------------
// Kernel 3: output projection.
// ---------------------------------------------------------------------------
__global__ __launch_bounds__(256, 2) void out_gemm_tc(
    const float* __restrict__ bO, float* __restrict__ out)
{
    extern __shared__ __half sg[];
    __half* As = sg;
    __half* Bs = sg + 3 * A_ST;

    const int n0 = blockIdx.x * 128;
    const int m0 = blockIdx.y * 128;
    const int tid  = threadIdx.x;
    const int wid  = tid >> 5;
    const int lane = tid & 31;
    const int wm = wid >> 2;
    const int wn = wid & 3;
    const int g  = lane >> 2;
    const int t  = lane & 3;
    const int fa_r = lane & 15;
    const int fa_h = ((lane >> 4) & 1) * 8;
    const int fb_r = ((lane >> 4) & 1) * 8 + (lane & 7);
    const int fb_h = ((lane >> 3) & 1) * 8;

    float acc[4][4][4] = {};

    GEMM_ISSUE(g_z, g_wo, 0, 0); cp_commit();
    GEMM_ISSUE(g_z, g_wo, 1, 1); cp_commit();

    constexpr int NKT = DM / 32;
    for (int kt = 0; kt < NKT; ++kt) {
        cp_wait<1>();
        __syncthreads();
        if (kt + 2 < NKT) GEMM_ISSUE(g_z, g_wo, kt + 2, (kt + 2) % 3);
        cp_commit();
        GEMM_COMPUTE(kt % 3);
    }

#pragma unroll
    for (int mt = 0; mt < 4; mt++) {
#pragma unroll
        for (int nt = 0; nt < 4; nt++) {
            int mg = m0 + wm * 64 + mt * 16 + g;
            int c  = n0 + wn * 32 + nt * 8 + t * 2;
            float b0 = bO[c], b1 = bO[c + 1];
#pragma unroll
            for (int rr = 0; rr < 2; rr++) {
                float2 w;
                w.x = acc[mt][nt][rr * 2 + 0] + b0;
                w.y = acc[mt][nt][rr * 2 + 1] + b1;
                *(float2*)(out + (size_t)(mg + rr * 8) * DM + c) = w;
            }
        }
    }
}

// ---------------------------------------------------------------------------
// Launch
// ---------------------------------------------------------------------------
extern "C" void kernel_launch(void* const* d_in, const int* in_sizes, int n_in,
                              void* d_out, int out_size)
{
    const float* x  = (const float*)d_in[0];
    const float* Wq = (const float*)d_in[1];
    const float* bq = (const float*)d_in[2];
    const float* Wk = (const float*)d_in[3];
    const float* bk = (const float*)d_in[4];
    const float* Wv = (const float*)d_in[5];
    const float* bv = (const float*)d_in[6];
    const float* Wo = (const float*)d_in[7];
    const float* bo = (const float*)d_in[8];
    float* out = (float*)d_out;

    cudaFuncSetAttribute(qkv_gemm_tc,
                         cudaFuncAttributeMaxDynamicSharedMemorySize,
                         (int)GEMM_SMEM_BYTES);
    cudaFuncSetAttribute(out_gemm_tc,
                         cudaFuncAttributeMaxDynamicSharedMemorySize,
                         (int)GEMM_SMEM_BYTES);
    cudaFuncSetAttribute(flash_attn_tc,
                         cudaFuncAttributeMaxDynamicSharedMemorySize,
                         (int)SMEM_FLASH_BYTES);

    convert_x_kernel<<<(MROWS * DM / 4) / 256, 256>>>(x);
    convert_w_kernel<<<dim3((DM * DM / 2) / 256, 4), 256>>>(Wq, Wk, Wv, Wo);

    dim3 g1(DM / 128, MROWS / 128, 3);   // (8, 32, 3)
    qkv_gemm_tc<<<g1, 256, GEMM_SMEM_BYTES>>>(bq, bk, bv);

    dim3 g2(SEQ / 128, B_ * NH);          // (16, 32)
    flash_attn_tc<<<g2, 256, SMEM_FLASH_BYTES>>>();

    dim3 g3(DM / 128, MROWS / 128);       // (8, 32)
    out_gemm_tc<<<g3, 256, GEMM_SMEM_BYTES>>>(bo, out);
}